// round 1
// baseline (speedup 1.0000x reference)
#include <cuda_runtime.h>
#include <math.h>

#define S_LEN  2048
#define BATCH  2
#define DMODEL 1024
#define NH     16
#define HD     64

// Scratch (allocation-free requirement): qkv activations and attention output.
__device__ float g_qkv[BATCH * S_LEN * 3 * DMODEL];   // [b, s, 3d]  (~50 MB)
__device__ float g_att[BATCH * S_LEN * DMODEL];       // [b, s, d]   (~17 MB)

// ---------------------------------------------------------------------------
// Tiled SGEMM: C[M,N] = A[M,K] * B[N,K]^T + bias[N]
// A, B row-major (both K-contiguous -> "NT" gemm, matches torch Linear weight)
// 128x128 tile, BK=16, 256 threads, 8x8 register blocking.
// ---------------------------------------------------------------------------
template<int M_, int N_, int K_>
__global__ __launch_bounds__(256)
void gemm_abt_bias(const float* __restrict__ A, const float* __restrict__ B,
                   const float* __restrict__ bias, float* __restrict__ C)
{
    constexpr int BM = 128, BN = 128, BK = 16;
    __shared__ float As[BK][BM + 4];  // transposed: As[k][m]
    __shared__ float Bs[BK][BN + 4];  // transposed: Bs[k][n]

    const int tid = threadIdx.x;
    const int tx  = tid & 15;        // 0..15  -> N direction
    const int ty  = tid >> 4;        // 0..15  -> M direction
    const int mBase = blockIdx.y * BM;
    const int nBase = blockIdx.x * BN;

    float acc[8][8];
    #pragma unroll
    for (int i = 0; i < 8; i++)
        #pragma unroll
        for (int j = 0; j < 8; j++) acc[i][j] = 0.0f;

    for (int k0 = 0; k0 < K_; k0 += BK) {
        // Load A tile (128x16) and B tile (128x16), store transposed.
        #pragma unroll
        for (int i = 0; i < 2; i++) {
            int f   = tid + i * 256;          // 0..511 float4 slots
            int row = f >> 2;                  // 0..127
            int c4  = (f & 3) * 4;             // 0,4,8,12
            float4 a = *(const float4*)(A + (size_t)(mBase + row) * K_ + k0 + c4);
            As[c4 + 0][row] = a.x; As[c4 + 1][row] = a.y;
            As[c4 + 2][row] = a.z; As[c4 + 3][row] = a.w;
            float4 bb = *(const float4*)(B + (size_t)(nBase + row) * K_ + k0 + c4);
            Bs[c4 + 0][row] = bb.x; Bs[c4 + 1][row] = bb.y;
            Bs[c4 + 2][row] = bb.z; Bs[c4 + 3][row] = bb.w;
        }
        __syncthreads();

        #pragma unroll
        for (int k = 0; k < BK; k++) {
            float a[8], b[8];
            *(float4*)&a[0] = *(const float4*)&As[k][ty * 8];
            *(float4*)&a[4] = *(const float4*)&As[k][ty * 8 + 4];
            *(float4*)&b[0] = *(const float4*)&Bs[k][tx * 8];
            *(float4*)&b[4] = *(const float4*)&Bs[k][tx * 8 + 4];
            #pragma unroll
            for (int i = 0; i < 8; i++)
                #pragma unroll
                for (int j = 0; j < 8; j++)
                    acc[i][j] = fmaf(a[i], b[j], acc[i][j]);
        }
        __syncthreads();
    }

    float bv[8];
    #pragma unroll
    for (int j = 0; j < 8; j++) bv[j] = bias[nBase + tx * 8 + j];

    #pragma unroll
    for (int i = 0; i < 8; i++) {
        int row = mBase + ty * 8 + i;
        float4 r0, r1;
        r0.x = acc[i][0] + bv[0]; r0.y = acc[i][1] + bv[1];
        r0.z = acc[i][2] + bv[2]; r0.w = acc[i][3] + bv[3];
        r1.x = acc[i][4] + bv[4]; r1.y = acc[i][5] + bv[5];
        r1.z = acc[i][6] + bv[6]; r1.w = acc[i][7] + bv[7];
        *(float4*)(C + (size_t)row * N_ + nBase + tx * 8)     = r0;
        *(float4*)(C + (size_t)row * N_ + nBase + tx * 8 + 4) = r1;
    }
}

// ---------------------------------------------------------------------------
// Flash attention, fp32. One block = (b, h, 128-query tile). 256 threads.
// Thread (rg,cg) with rg=tid>>3 (0..31), cg=tid&7 (0..7) owns a 4x8 micro-tile.
// Q/K stored d-major in smem so fragments are contiguous float4 loads.
// ---------------------------------------------------------------------------
__global__ __launch_bounds__(256)
void flash_attn(const float* __restrict__ qkv, float* __restrict__ out,
                const int* __restrict__ causal_flag)
{
    constexpr int BM = 128, BN = 64;
    constexpr int QT_LD = 132;   // [64][132]
    constexpr int KT_LD = 68;    // [64][68]
    constexpr int VS_LD = 68;    // [64][68]
    constexpr int PT_LD = 132;   // [64][132]

    extern __shared__ float smem[];
    float* Qt = smem;                    // Qt[d][m]
    float* Kt = Qt + 64 * QT_LD;         // Kt[d][n]
    float* Vs = Kt + 64 * KT_LD;         // Vs[j][c]
    float* Pt = Vs + 64 * VS_LD;         // Pt[j][m]

    const int tid   = threadIdx.x;
    const int qTile = blockIdx.x;        // 0..15
    const int h     = blockIdx.y;        // 0..15
    const int b     = blockIdx.z;        // 0..1
    const int qBase = qTile * BM;
    const bool causal = (*causal_flag != 0);

    const int rg = tid >> 3;             // 0..31 (row group of 4)
    const int cg = tid & 7;              // 0..7  (col group of 8)

    const int rowStride = 3 * DMODEL;
    const float* qp = qkv + (size_t)b * S_LEN * rowStride + h * HD;
    const float* kp = qp + DMODEL;
    const float* vp = qp + 2 * DMODEL;

    // Load Q tile, transposed to d-major.
    for (int idx = tid; idx < BM * HD; idx += 256) {
        int m = idx >> 6;
        int d = idx & 63;
        Qt[d * QT_LD + m] = qp[(size_t)(qBase + m) * rowStride + d];
    }

    float o[4][8];
    float mrow[4], lrow[4];
    #pragma unroll
    for (int i = 0; i < 4; i++) {
        mrow[i] = -1e30f; lrow[i] = 0.0f;
        #pragma unroll
        for (int j = 0; j < 8; j++) o[i][j] = 0.0f;
    }

    int nTiles = S_LEN / BN;                       // 32
    if (causal) nTiles = (qBase + BM) / BN;        // only tiles with keys <= last query

    for (int t = 0; t < nTiles; t++) {
        const int kBase = t * BN;

        // Load K (d-major) and V (j-major) tiles.
        for (int idx = tid; idx < BN * HD; idx += 256) {
            int n = idx >> 6;
            int d = idx & 63;
            float kv = kp[(size_t)(kBase + n) * rowStride + d];
            float vv = vp[(size_t)(kBase + n) * rowStride + d];
            Kt[d * KT_LD + n] = kv;
            Vs[n * VS_LD + d] = vv;
        }
        __syncthreads();

        // Phase A: S = Q K^T (4x8 per thread)
        float s[4][8];
        #pragma unroll
        for (int i = 0; i < 4; i++)
            #pragma unroll
            for (int j = 0; j < 8; j++) s[i][j] = 0.0f;

        #pragma unroll 8
        for (int d = 0; d < HD; d++) {
            float4 q  = *(const float4*)&Qt[d * QT_LD + rg * 4];
            float4 k0 = *(const float4*)&Kt[d * KT_LD + cg * 8];
            float4 k1 = *(const float4*)&Kt[d * KT_LD + cg * 8 + 4];
            float qa[4] = {q.x, q.y, q.z, q.w};
            float kb[8] = {k0.x, k0.y, k0.z, k0.w, k1.x, k1.y, k1.z, k1.w};
            #pragma unroll
            for (int i = 0; i < 4; i++)
                #pragma unroll
                for (int j = 0; j < 8; j++)
                    s[i][j] = fmaf(qa[i], kb[j], s[i][j]);
        }

        // Scale + optional causal mask.
        const float sc = 0.125f;   // 1/sqrt(64)
        #pragma unroll
        for (int i = 0; i < 4; i++) {
            int qi = qBase + rg * 4 + i;
            #pragma unroll
            for (int j = 0; j < 8; j++) {
                float v = s[i][j] * sc;
                if (causal && (kBase + cg * 8 + j > qi)) v = -1e30f;
                s[i][j] = v;
            }
        }

        // Online softmax (row spread across 8 consecutive lanes).
        #pragma unroll
        for (int i = 0; i < 4; i++) {
            float tm = s[i][0];
            #pragma unroll
            for (int j = 1; j < 8; j++) tm = fmaxf(tm, s[i][j]);
            #pragma unroll
            for (int off = 1; off < 8; off <<= 1)
                tm = fmaxf(tm, __shfl_xor_sync(0xffffffffu, tm, off));
            float mnew  = fmaxf(mrow[i], tm);
            float alpha = __expf(mrow[i] - mnew);
            mrow[i] = mnew;
            float rs = 0.0f;
            #pragma unroll
            for (int j = 0; j < 8; j++) {
                float p = __expf(s[i][j] - mnew);
                s[i][j] = p;
                rs += p;
            }
            #pragma unroll
            for (int off = 1; off < 8; off <<= 1)
                rs += __shfl_xor_sync(0xffffffffu, rs, off);
            lrow[i] = lrow[i] * alpha + rs;
            #pragma unroll
            for (int j = 0; j < 8; j++) o[i][j] *= alpha;
        }

        // Write P transposed (j-major) for the PV gemm.
        #pragma unroll
        for (int i = 0; i < 4; i++)
            #pragma unroll
            for (int j = 0; j < 8; j++)
                Pt[(cg * 8 + j) * PT_LD + rg * 4 + i] = s[i][j];
        __syncthreads();

        // Phase C: O += P V
        #pragma unroll 8
        for (int j = 0; j < BN; j++) {
            float4 p  = *(const float4*)&Pt[j * PT_LD + rg * 4];
            float4 v0 = *(const float4*)&Vs[j * VS_LD + cg * 8];
            float4 v1 = *(const float4*)&Vs[j * VS_LD + cg * 8 + 4];
            float pa[4] = {p.x, p.y, p.z, p.w};
            float vb[8] = {v0.x, v0.y, v0.z, v0.w, v1.x, v1.y, v1.z, v1.w};
            #pragma unroll
            for (int i = 0; i < 4; i++)
                #pragma unroll
                for (int jj = 0; jj < 8; jj++)
                    o[i][jj] = fmaf(pa[i], vb[jj], o[i][jj]);
        }
        __syncthreads();
    }

    // Epilogue: normalize and store to [b, s, h*64 + c].
    float* op = out + (size_t)b * S_LEN * DMODEL + h * HD;
    #pragma unroll
    for (int i = 0; i < 4; i++) {
        float inv = 1.0f / lrow[i];
        int r = qBase + rg * 4 + i;
        float4 r0, r1;
        r0.x = o[i][0] * inv; r0.y = o[i][1] * inv;
        r0.z = o[i][2] * inv; r0.w = o[i][3] * inv;
        r1.x = o[i][4] * inv; r1.y = o[i][5] * inv;
        r1.z = o[i][6] * inv; r1.w = o[i][7] * inv;
        *(float4*)(op + (size_t)r * DMODEL + cg * 8)     = r0;
        *(float4*)(op + (size_t)r * DMODEL + cg * 8 + 4) = r1;
    }
}

// ---------------------------------------------------------------------------
extern "C" void kernel_launch(void* const* d_in, const int* in_sizes, int n_in,
                              void* d_out, int out_size)
{
    (void)in_sizes; (void)n_in; (void)out_size;
    const float* features = (const float*)d_in[0];
    const float* qkv_w    = (const float*)d_in[1];
    const float* qkv_b    = (const float*)d_in[2];
    const float* out_w    = (const float*)d_in[3];
    const float* out_b    = (const float*)d_in[4];
    const int*   causal   = (const int*)d_in[5];
    float* out = (float*)d_out;

    float* qkvbuf = nullptr;
    float* attbuf = nullptr;
    cudaGetSymbolAddress((void**)&qkvbuf, g_qkv);
    cudaGetSymbolAddress((void**)&attbuf, g_att);

    const int SMEM_FLASH = 64 * (132 + 68 + 68 + 132) * (int)sizeof(float); // 102400 B
    cudaFuncSetAttribute(flash_attn, cudaFuncAttributeMaxDynamicSharedMemorySize,
                         SMEM_FLASH);

    // 1) QKV projection: [4096,1024] x [3072,1024]^T
    gemm_abt_bias<BATCH * S_LEN, 3 * DMODEL, DMODEL>
        <<<dim3(3 * DMODEL / 128, BATCH * S_LEN / 128), 256>>>(
            features, qkv_w, qkv_b, qkvbuf);

    // 2) Attention
    flash_attn<<<dim3(S_LEN / 128, NH, BATCH), 256, SMEM_FLASH>>>(
        qkvbuf, attbuf, causal);

    // 3) Output projection: [4096,1024] x [1024,1024]^T
    gemm_abt_bias<BATCH * S_LEN, DMODEL, DMODEL>
        <<<dim3(DMODEL / 128, BATCH * S_LEN / 128), 256>>>(
            attbuf, out_w, out_b, out);
}

// round 2
// speedup vs baseline: 3.0981x; 3.0981x over previous
#include <cuda_runtime.h>
#include <math.h>

#define S_LEN  2048
#define BATCH  2
#define DMODEL 1024
#define NH     16
#define HD     64

// Scratch (allocation-free requirement)
__device__ float g_qkv[BATCH * S_LEN * 3 * DMODEL];   // [b, s, 3d]
__device__ float g_att[BATCH * S_LEN * DMODEL];       // [b, s, d]

// ---------------------------------------------------------------------------
// helpers
// ---------------------------------------------------------------------------
__device__ __forceinline__ unsigned f2tf32(float f) {
    unsigned u;
    asm("cvt.rna.tf32.f32 %0, %1;" : "=r"(u) : "f"(f));
    return u;
}
__device__ __forceinline__ float tf32f(float f) {
    return __uint_as_float(f2tf32(f));
}
__device__ __forceinline__ void mma_tf32(float c[4], unsigned a0, unsigned a1,
                                         unsigned a2, unsigned a3,
                                         unsigned b0, unsigned b1) {
    asm("mma.sync.aligned.m16n8k8.row.col.f32.tf32.tf32.f32 "
        "{%0,%1,%2,%3}, {%4,%5,%6,%7}, {%8,%9}, {%0,%1,%2,%3};"
        : "+f"(c[0]), "+f"(c[1]), "+f"(c[2]), "+f"(c[3])
        : "r"(a0), "r"(a1), "r"(a2), "r"(a3), "r"(b0), "r"(b1));
}

// ---------------------------------------------------------------------------
// TF32 tensor-core GEMM: C[M,N] = A[M,K] * B[N,K]^T + bias[N]
// 128x128x32 block tile, 256 threads, 8 warps (2M x 4N), 4x4 mma tiles/warp.
// smem [row][k], stride 36 -> conflict-free fragment LDS.
// ---------------------------------------------------------------------------
template<int N_, int K_>
__global__ __launch_bounds__(256, 1)
void gemm_tc(const float* __restrict__ A, const float* __restrict__ B,
             const float* __restrict__ bias, float* __restrict__ C)
{
    __shared__ float As[128 * 36];
    __shared__ float Bs[128 * 36];

    const int tid  = threadIdx.x;
    const int warp = tid >> 5;
    const int lane = tid & 31;
    const int gid  = lane >> 2;
    const int tig  = lane & 3;
    const int warpM = (warp & 1) * 64;
    const int warpN = (warp >> 1) * 32;
    const int mBase = blockIdx.y * 128;
    const int nBase = blockIdx.x * 128;

    float acc[16][4];
    #pragma unroll
    for (int i = 0; i < 16; i++)
        #pragma unroll
        for (int j = 0; j < 4; j++) acc[i][j] = 0.0f;

    for (int k0 = 0; k0 < K_; k0 += 32) {
        #pragma unroll
        for (int i = 0; i < 4; i++) {
            int s4  = tid + i * 256;        // float4 slot: 1024 slots
            int row = s4 >> 3;              // 0..127
            int c   = (s4 & 7) * 4;         // 0..28
            float4 a = *(const float4*)(A + (size_t)(mBase + row) * K_ + k0 + c);
            As[row * 36 + c + 0] = tf32f(a.x);
            As[row * 36 + c + 1] = tf32f(a.y);
            As[row * 36 + c + 2] = tf32f(a.z);
            As[row * 36 + c + 3] = tf32f(a.w);
            float4 bb = *(const float4*)(B + (size_t)(nBase + row) * K_ + k0 + c);
            Bs[row * 36 + c + 0] = tf32f(bb.x);
            Bs[row * 36 + c + 1] = tf32f(bb.y);
            Bs[row * 36 + c + 2] = tf32f(bb.z);
            Bs[row * 36 + c + 3] = tf32f(bb.w);
        }
        __syncthreads();

        #pragma unroll
        for (int ks = 0; ks < 4; ks++) {
            unsigned afr[4][4], bfr[4][2];
            #pragma unroll
            for (int mt = 0; mt < 4; mt++) {
                int m = warpM + mt * 16 + gid;
                int k = ks * 8 + tig;
                afr[mt][0] = __float_as_uint(As[m * 36 + k]);
                afr[mt][1] = __float_as_uint(As[(m + 8) * 36 + k]);
                afr[mt][2] = __float_as_uint(As[m * 36 + k + 4]);
                afr[mt][3] = __float_as_uint(As[(m + 8) * 36 + k + 4]);
            }
            #pragma unroll
            for (int nt = 0; nt < 4; nt++) {
                int n = warpN + nt * 8 + gid;
                int k = ks * 8 + tig;
                bfr[nt][0] = __float_as_uint(Bs[n * 36 + k]);
                bfr[nt][1] = __float_as_uint(Bs[n * 36 + k + 4]);
            }
            #pragma unroll
            for (int mt = 0; mt < 4; mt++)
                #pragma unroll
                for (int nt = 0; nt < 4; nt++)
                    mma_tf32(acc[mt * 4 + nt], afr[mt][0], afr[mt][1],
                             afr[mt][2], afr[mt][3], bfr[nt][0], bfr[nt][1]);
        }
        __syncthreads();
    }

    #pragma unroll
    for (int mt = 0; mt < 4; mt++) {
        #pragma unroll
        for (int nt = 0; nt < 4; nt++) {
            int row  = mBase + warpM + mt * 16 + gid;
            int coln = nBase + warpN + nt * 8 + 2 * tig;
            float b0 = bias[coln], b1 = bias[coln + 1];
            float* acc4 = acc[mt * 4 + nt];
            float2 w0 = {acc4[0] + b0, acc4[1] + b1};
            float2 w1 = {acc4[2] + b0, acc4[3] + b1};
            *(float2*)(C + (size_t)row * N_ + coln)       = w0;
            *(float2*)(C + (size_t)(row + 8) * N_ + coln) = w1;
        }
    }
}

// ---------------------------------------------------------------------------
// TF32 tensor-core flash attention.
// Block = (b, h, 128-query tile), 256 threads, 8 warps.
// Warp w owns query rows [w*16, w*16+16): softmax rows never cross warps.
// Per key tile (64 keys): S = Q K^T (mma), online softmax in C-fragments,
// P fragments built from S fragments via in-register shuffles, O += P V (mma).
// ---------------------------------------------------------------------------
__global__ __launch_bounds__(256, 1)
void flash_attn_tc(const float* __restrict__ qkv, float* __restrict__ out,
                   const int* __restrict__ causal_flag)
{
    constexpr int QLD = 68, KLD = 68, VLD = 72;
    extern __shared__ float smem[];
    float* Qs = smem;                 // [128][68]  (tf32 values)
    float* Ks = Qs + 128 * QLD;       // [64][68]
    float* Vs = Ks + 64 * KLD;        // [64][72]

    const int tid  = threadIdx.x;
    const int warp = tid >> 5;
    const int lane = tid & 31;
    const int gid  = lane >> 2;
    const int tig  = lane & 3;
    const int qBase = blockIdx.x * 128;
    const int h = blockIdx.y;
    const int b = blockIdx.z;
    const bool causal = (*causal_flag != 0);

    const int rowStride = 3 * DMODEL;
    const float* qp = qkv + (size_t)b * S_LEN * rowStride + h * HD;
    const float* kp = qp + DMODEL;
    const float* vp = qp + 2 * DMODEL;

    // Load Q tile (128x64), tf32-converted.
    #pragma unroll
    for (int i = 0; i < 8; i++) {
        int s4 = tid + i * 256;       // 2048 float4 slots
        int m  = s4 >> 4;
        int c  = (s4 & 15) * 4;
        float4 v = *(const float4*)(qp + (size_t)(qBase + m) * rowStride + c);
        Qs[m * QLD + c + 0] = tf32f(v.x);
        Qs[m * QLD + c + 1] = tf32f(v.y);
        Qs[m * QLD + c + 2] = tf32f(v.z);
        Qs[m * QLD + c + 3] = tf32f(v.w);
    }

    float of[8][4];
    #pragma unroll
    for (int i = 0; i < 8; i++)
        #pragma unroll
        for (int j = 0; j < 4; j++) of[i][j] = 0.0f;
    float mrow0 = -1e30f, mrow1 = -1e30f, lrow0 = 0.0f, lrow1 = 0.0f;

    const int row0g = qBase + warp * 16 + gid;   // global query row (and +8)

    int nTiles = S_LEN / 64;
    if (causal) nTiles = (qBase + 128) / 64;

    for (int t = 0; t < nTiles; t++) {
        const int kBase = t * 64;

        // Load K, V tiles (64x64 each), tf32-converted.
        #pragma unroll
        for (int i = 0; i < 4; i++) {
            int s4 = tid + i * 256;   // 1024 slots
            int n  = s4 >> 4;
            int c  = (s4 & 15) * 4;
            float4 kv = *(const float4*)(kp + (size_t)(kBase + n) * rowStride + c);
            Ks[n * KLD + c + 0] = tf32f(kv.x);
            Ks[n * KLD + c + 1] = tf32f(kv.y);
            Ks[n * KLD + c + 2] = tf32f(kv.z);
            Ks[n * KLD + c + 3] = tf32f(kv.w);
            float4 vv = *(const float4*)(vp + (size_t)(kBase + n) * rowStride + c);
            Vs[n * VLD + c + 0] = tf32f(vv.x);
            Vs[n * VLD + c + 1] = tf32f(vv.y);
            Vs[n * VLD + c + 2] = tf32f(vv.z);
            Vs[n * VLD + c + 3] = tf32f(vv.w);
        }
        __syncthreads();

        // ---- Phase A: S = Q K^T ----
        float sc[8][4];
        #pragma unroll
        for (int i = 0; i < 8; i++)
            #pragma unroll
            for (int j = 0; j < 4; j++) sc[i][j] = 0.0f;

        #pragma unroll
        for (int ks = 0; ks < 8; ks++) {
            int m = warp * 16 + gid;
            int k = ks * 8 + tig;
            unsigned a0 = __float_as_uint(Qs[m * QLD + k]);
            unsigned a1 = __float_as_uint(Qs[(m + 8) * QLD + k]);
            unsigned a2 = __float_as_uint(Qs[m * QLD + k + 4]);
            unsigned a3 = __float_as_uint(Qs[(m + 8) * QLD + k + 4]);
            #pragma unroll
            for (int nt = 0; nt < 8; nt++) {
                int n = nt * 8 + gid;
                unsigned b0 = __float_as_uint(Ks[n * KLD + k]);
                unsigned b1 = __float_as_uint(Ks[n * KLD + k + 4]);
                mma_tf32(sc[nt], a0, a1, a2, a3, b0, b1);
            }
        }

        // ---- online softmax (rows gid and gid+8, spread over quad lanes) ----
        const float scale = 0.125f;
        float ml0 = -1e30f, ml1 = -1e30f;
        #pragma unroll
        for (int nt = 0; nt < 8; nt++) {
            int coln = kBase + nt * 8 + 2 * tig;
            #pragma unroll
            for (int cc = 0; cc < 4; cc++) {
                float v = sc[nt][cc] * scale;
                if (causal) {
                    int col = coln + (cc & 1);
                    int row = (cc < 2) ? row0g : (row0g + 8);
                    if (col > row) v = -1e30f;
                }
                sc[nt][cc] = v;
                if (cc < 2) ml0 = fmaxf(ml0, v);
                else        ml1 = fmaxf(ml1, v);
            }
        }
        #pragma unroll
        for (int off = 1; off < 4; off <<= 1) {
            ml0 = fmaxf(ml0, __shfl_xor_sync(0xffffffffu, ml0, off));
            ml1 = fmaxf(ml1, __shfl_xor_sync(0xffffffffu, ml1, off));
        }
        float mn0 = fmaxf(mrow0, ml0), mn1 = fmaxf(mrow1, ml1);
        float al0 = __expf(mrow0 - mn0), al1 = __expf(mrow1 - mn1);
        mrow0 = mn0; mrow1 = mn1;

        float rs0 = 0.0f, rs1 = 0.0f;
        #pragma unroll
        for (int nt = 0; nt < 8; nt++) {
            float p0 = __expf(sc[nt][0] - mn0);
            float p1 = __expf(sc[nt][1] - mn0);
            float p2 = __expf(sc[nt][2] - mn1);
            float p3 = __expf(sc[nt][3] - mn1);
            sc[nt][0] = p0; sc[nt][1] = p1; sc[nt][2] = p2; sc[nt][3] = p3;
            rs0 += p0 + p1; rs1 += p2 + p3;
        }
        #pragma unroll
        for (int off = 1; off < 4; off <<= 1) {
            rs0 += __shfl_xor_sync(0xffffffffu, rs0, off);
            rs1 += __shfl_xor_sync(0xffffffffu, rs1, off);
        }
        lrow0 = lrow0 * al0 + rs0;
        lrow1 = lrow1 * al1 + rs1;
        #pragma unroll
        for (int dt = 0; dt < 8; dt++) {
            of[dt][0] *= al0; of[dt][1] *= al0;
            of[dt][2] *= al1; of[dt][3] *= al1;
        }

        // ---- Phase B: O += P V ----
        const int l0 = (lane & 28) | (tig >> 1);
        const int l1 = l0 + 2;
        const bool odd = (tig & 1);
        #pragma unroll
        for (int kt = 0; kt < 8; kt++) {
            // C-fragment -> A-fragment layout conversion via shuffles
            float p00 = __shfl_sync(0xffffffffu, sc[kt][0], l0);
            float p01 = __shfl_sync(0xffffffffu, sc[kt][1], l0);
            float p10 = __shfl_sync(0xffffffffu, sc[kt][2], l0);
            float p11 = __shfl_sync(0xffffffffu, sc[kt][3], l0);
            float q00 = __shfl_sync(0xffffffffu, sc[kt][0], l1);
            float q01 = __shfl_sync(0xffffffffu, sc[kt][1], l1);
            float q10 = __shfl_sync(0xffffffffu, sc[kt][2], l1);
            float q11 = __shfl_sync(0xffffffffu, sc[kt][3], l1);
            unsigned a0 = f2tf32(odd ? p01 : p00);
            unsigned a1 = f2tf32(odd ? p11 : p10);
            unsigned a2 = f2tf32(odd ? q01 : q00);
            unsigned a3 = f2tf32(odd ? q11 : q10);
            #pragma unroll
            for (int dt = 0; dt < 8; dt++) {
                unsigned b0 = __float_as_uint(Vs[(kt * 8 + tig) * VLD + dt * 8 + gid]);
                unsigned b1 = __float_as_uint(Vs[(kt * 8 + tig + 4) * VLD + dt * 8 + gid]);
                mma_tf32(of[dt], a0, a1, a2, a3, b0, b1);
            }
        }
        __syncthreads();
    }

    // Epilogue: normalize, store to [b, s, h*64 + d]
    float inv0 = 1.0f / lrow0, inv1 = 1.0f / lrow1;
    float* op = out + (size_t)b * S_LEN * DMODEL + h * HD;
    #pragma unroll
    for (int dt = 0; dt < 8; dt++) {
        int col = dt * 8 + 2 * tig;
        float2 w0 = {of[dt][0] * inv0, of[dt][1] * inv0};
        float2 w1 = {of[dt][2] * inv1, of[dt][3] * inv1};
        *(float2*)(op + (size_t)row0g * DMODEL + col)       = w0;
        *(float2*)(op + (size_t)(row0g + 8) * DMODEL + col) = w1;
    }
}

// ---------------------------------------------------------------------------
extern "C" void kernel_launch(void* const* d_in, const int* in_sizes, int n_in,
                              void* d_out, int out_size)
{
    (void)in_sizes; (void)n_in; (void)out_size;
    const float* features = (const float*)d_in[0];
    const float* qkv_w    = (const float*)d_in[1];
    const float* qkv_b    = (const float*)d_in[2];
    const float* out_w    = (const float*)d_in[3];
    const float* out_b    = (const float*)d_in[4];
    const int*   causal   = (const int*)d_in[5];
    float* out = (float*)d_out;

    float* qkvbuf = nullptr;
    float* attbuf = nullptr;
    cudaGetSymbolAddress((void**)&qkvbuf, g_qkv);
    cudaGetSymbolAddress((void**)&attbuf, g_att);

    const int SMEM_FLASH = (128 * 68 + 64 * 68 + 64 * 72) * (int)sizeof(float); // 70656
    cudaFuncSetAttribute(flash_attn_tc, cudaFuncAttributeMaxDynamicSharedMemorySize,
                         SMEM_FLASH);

    // 1) QKV projection: [4096,1024] x [3072,1024]^T
    gemm_tc<3 * DMODEL, DMODEL>
        <<<dim3(3 * DMODEL / 128, BATCH * S_LEN / 128), 256>>>(
            features, qkv_w, qkv_b, qkvbuf);

    // 2) Attention
    flash_attn_tc<<<dim3(S_LEN / 128, NH, BATCH), 256, SMEM_FLASH>>>(
        qkvbuf, attbuf, causal);

    // 3) Output projection: [4096,1024] x [1024,1024]^T
    gemm_tc<DMODEL, DMODEL>
        <<<dim3(DMODEL / 128, BATCH * S_LEN / 128), 256>>>(
            attbuf, out_w, out_b, out);
}

// round 7
// speedup vs baseline: 3.6017x; 1.1626x over previous
#include <cuda_runtime.h>
#include <cstdint>
#include <stdint.h>
#include <math.h>

#define S_LEN  2048
#define BATCH  2
#define DMODEL 1024
#define NH     16
#define HD     64

// Scratch (allocation-free requirement)
__device__ float g_qkv[BATCH * S_LEN * 3 * DMODEL];   // [b, s, 3d]
__device__ float g_att[BATCH * S_LEN * DMODEL];       // [b, s, d]

// ---------------------------------------------------------------------------
// helpers
// ---------------------------------------------------------------------------
__device__ __forceinline__ unsigned f2tf32(float f) {
    unsigned u;
    asm("cvt.rna.tf32.f32 %0, %1;" : "=r"(u) : "f"(f));
    return u;
}
__device__ __forceinline__ void mma_tf32(float c[4], unsigned a0, unsigned a1,
                                         unsigned a2, unsigned a3,
                                         unsigned b0, unsigned b1) {
    asm("mma.sync.aligned.m16n8k8.row.col.f32.tf32.tf32.f32 "
        "{%0,%1,%2,%3}, {%4,%5,%6,%7}, {%8,%9}, {%0,%1,%2,%3};"
        : "+f"(c[0]), "+f"(c[1]), "+f"(c[2]), "+f"(c[3])
        : "r"(a0), "r"(a1), "r"(a2), "r"(a3), "r"(b0), "r"(b1));
}
__device__ __forceinline__ void cp_async16(unsigned int dst, const void* src) {
    asm volatile("cp.async.cg.shared.global [%0], [%1], 16;" :: "r"(dst), "l"(src));
}
__device__ __forceinline__ void cp_commit() {
    asm volatile("cp.async.commit_group;");
}
template<int N>
__device__ __forceinline__ void cp_wait() {
    asm volatile("cp.async.wait_group %0;" :: "n"(N));
}

// ---------------------------------------------------------------------------
// TF32 tensor-core GEMM with 3-stage cp.async pipeline.
// C[M,N] = A[M,K] * B[N,K]^T + bias[N]
// 128x128x32 block tile, 256 threads, 8 warps (2M x 4N), 4x4 mma tiles/warp.
// smem [row][k] raw fp32, stride 36; tf32 cvt per-fragment after LDS.
// Tail iterations drain with wait_group 0.
// ---------------------------------------------------------------------------
#define GSTG (128 * 36)        // floats per (A or B) tile
#define GSTAGE (2 * GSTG)      // floats per pipeline stage
#define GSTAGES 3

template<int N_, int K_>
__global__ __launch_bounds__(256, 1)
void gemm_tc(const float* __restrict__ A, const float* __restrict__ B,
             const float* __restrict__ bias, float* __restrict__ C)
{
    extern __shared__ float sm[];
    const unsigned int smAddr = (unsigned int)__cvta_generic_to_shared(sm);

    const int tid  = threadIdx.x;
    const int warp = tid >> 5;
    const int lane = tid & 31;
    const int gid  = lane >> 2;
    const int tig  = lane & 3;
    const int warpM = (warp & 1) * 64;
    const int warpN = (warp >> 1) * 32;
    const int mBase = blockIdx.y * 128;
    const int nBase = blockIdx.x * 128;

    // 128x32 tile = 4096 floats = 1024 float4 slots -> 4 per thread
    int lrow[4], lcol[4];
    #pragma unroll
    for (int i = 0; i < 4; i++) {
        int s4 = tid + i * 256;
        lrow[i] = s4 >> 3;
        lcol[i] = (s4 & 7) * 4;
    }

    auto issue_stage = [&](int stage, int k0) {
        unsigned int aB = smAddr + stage * GSTAGE * 4;
        unsigned int bB = aB + GSTG * 4;
        #pragma unroll
        for (int i = 0; i < 4; i++) {
            unsigned int off = (lrow[i] * 36 + lcol[i]) * 4;
            cp_async16(aB + off, A + (size_t)(mBase + lrow[i]) * K_ + k0 + lcol[i]);
            cp_async16(bB + off, B + (size_t)(nBase + lrow[i]) * K_ + k0 + lcol[i]);
        }
    };

    float acc[16][4];
    #pragma unroll
    for (int i = 0; i < 16; i++)
        #pragma unroll
        for (int j = 0; j < 4; j++) acc[i][j] = 0.0f;

    const int kTiles = K_ / 32;
    #pragma unroll
    for (int s = 0; s < GSTAGES - 1; s++) {
        issue_stage(s, s * 32);
        cp_commit();
    }

    for (int kt = 0; kt < kTiles; kt++) {
        if (kt + GSTAGES - 1 < kTiles) {
            issue_stage((kt + GSTAGES - 1) % GSTAGES, (kt + GSTAGES - 1) * 32);
            cp_commit();
            cp_wait<GSTAGES - 1>();   // tile kt complete
        } else {
            cp_wait<0>();             // tail: drain everything still in flight
        }
        __syncthreads();

        const float* As = sm + (kt % GSTAGES) * GSTAGE;
        const float* Bs = As + GSTG;

        #pragma unroll
        for (int ks = 0; ks < 4; ks++) {
            unsigned afr[4][4], bfr[4][2];
            #pragma unroll
            for (int mt = 0; mt < 4; mt++) {
                int m = warpM + mt * 16 + gid;
                int k = ks * 8 + tig;
                afr[mt][0] = f2tf32(As[m * 36 + k]);
                afr[mt][1] = f2tf32(As[(m + 8) * 36 + k]);
                afr[mt][2] = f2tf32(As[m * 36 + k + 4]);
                afr[mt][3] = f2tf32(As[(m + 8) * 36 + k + 4]);
            }
            #pragma unroll
            for (int nt = 0; nt < 4; nt++) {
                int n = warpN + nt * 8 + gid;
                int k = ks * 8 + tig;
                bfr[nt][0] = f2tf32(Bs[n * 36 + k]);
                bfr[nt][1] = f2tf32(Bs[n * 36 + k + 4]);
            }
            #pragma unroll
            for (int mt = 0; mt < 4; mt++)
                #pragma unroll
                for (int nt = 0; nt < 4; nt++)
                    mma_tf32(acc[mt * 4 + nt], afr[mt][0], afr[mt][1],
                             afr[mt][2], afr[mt][3], bfr[nt][0], bfr[nt][1]);
        }
        __syncthreads();
    }

    #pragma unroll
    for (int mt = 0; mt < 4; mt++) {
        #pragma unroll
        for (int nt = 0; nt < 4; nt++) {
            int row  = mBase + warpM + mt * 16 + gid;
            int coln = nBase + warpN + nt * 8 + 2 * tig;
            float b0 = bias[coln], b1 = bias[coln + 1];
            float* acc4 = acc[mt * 4 + nt];
            float2 w0 = {acc4[0] + b0, acc4[1] + b1};
            float2 w1 = {acc4[2] + b0, acc4[3] + b1};
            *(float2*)(C + (size_t)row * N_ + coln)       = w0;
            *(float2*)(C + (size_t)(row + 8) * N_ + coln) = w1;
        }
    }
}

// ---------------------------------------------------------------------------
// TF32 tensor-core flash attention with double-buffered cp.async K/V tiles.
// Block = (b, h, 128-query tile), 256 threads, 8 warps.
// Warp w owns query rows [w*16, w*16+16).
// ---------------------------------------------------------------------------
#define QLD 68
#define KLD 68
#define VLD 72
#define Q_FLOATS (128 * QLD)
#define K_FLOATS (64 * KLD)
#define V_FLOATS (64 * VLD)

__global__ __launch_bounds__(256, 1)
void flash_attn_tc(const float* __restrict__ qkv, float* __restrict__ out,
                   const int* __restrict__ causal_flag)
{
    extern __shared__ float sm[];
    float* Qs = sm;                                  // [128][68] raw fp32
    float* Kbuf = Qs + Q_FLOATS;                     // 2 x [64][68]
    float* Vbuf = Kbuf + 2 * K_FLOATS;               // 2 x [64][72]
    const unsigned int smAddr = (unsigned int)__cvta_generic_to_shared(sm);
    const unsigned int kAddr0 = smAddr + Q_FLOATS * 4;
    const unsigned int vAddr0 = kAddr0 + 2 * K_FLOATS * 4;

    const int tid  = threadIdx.x;
    const int warp = tid >> 5;
    const int lane = tid & 31;
    const int gid  = lane >> 2;
    const int tig  = lane & 3;
    const int qBase = blockIdx.x * 128;
    const int h = blockIdx.y;
    const int b = blockIdx.z;
    const bool causal = (*causal_flag != 0);

    const int rowStride = 3 * DMODEL;
    const float* qp = qkv + (size_t)b * S_LEN * rowStride + h * HD;
    const float* kp = qp + DMODEL;
    const float* vp = qp + 2 * DMODEL;

    // 64x64 tile = 4096 floats = 1024 float4 slots -> 4 per thread
    // (R4/R6 bug: only 2/thread = rows 0..31 loaded, rows 32..63 stale)
    int kn[4], kc[4];
    #pragma unroll
    for (int i = 0; i < 4; i++) {
        int s4 = tid + i * 256;
        kn[i] = s4 >> 4;
        kc[i] = (s4 & 15) * 4;
    }
    auto issue_kv = [&](int buf, int kBase) {
        unsigned int kB = kAddr0 + buf * K_FLOATS * 4;
        unsigned int vB = vAddr0 + buf * V_FLOATS * 4;
        #pragma unroll
        for (int i = 0; i < 4; i++) {
            size_t g = (size_t)(kBase + kn[i]) * rowStride + kc[i];
            cp_async16(kB + (kn[i] * KLD + kc[i]) * 4, kp + g);
            cp_async16(vB + (kn[i] * VLD + kc[i]) * 4, vp + g);
        }
    };

    int nTiles = S_LEN / 64;
    if (causal) nTiles = (qBase + 128) / 64;

    issue_kv(0, 0);
    cp_commit();

    #pragma unroll
    for (int i = 0; i < 8; i++) {
        int s4 = tid + i * 256;
        int m  = s4 >> 4;
        int c  = (s4 & 15) * 4;
        *(float4*)&Qs[m * QLD + c] =
            *(const float4*)(qp + (size_t)(qBase + m) * rowStride + c);
    }

    float of[8][4];
    #pragma unroll
    for (int i = 0; i < 8; i++)
        #pragma unroll
        for (int j = 0; j < 4; j++) of[i][j] = 0.0f;
    float mrow0 = -1e30f, mrow1 = -1e30f, lrow0 = 0.0f, lrow1 = 0.0f;

    const int row0g = qBase + warp * 16 + gid;

    for (int t = 0; t < nTiles; t++) {
        const int kBase = t * 64;
        const int buf   = t & 1;

        if (t + 1 < nTiles) {
            issue_kv(1 - buf, kBase + 64);
            cp_commit();
            cp_wait<1>();        // tile t complete
        } else {
            cp_wait<0>();        // last tile: drain
        }
        __syncthreads();

        const float* Ks = Kbuf + buf * K_FLOATS;
        const float* Vs = Vbuf + buf * V_FLOATS;

        // ---- Phase A: S = Q K^T ----
        float sc[8][4];
        #pragma unroll
        for (int i = 0; i < 8; i++)
            #pragma unroll
            for (int j = 0; j < 4; j++) sc[i][j] = 0.0f;

        #pragma unroll
        for (int ks = 0; ks < 8; ks++) {
            int m = warp * 16 + gid;
            int k = ks * 8 + tig;
            unsigned a0 = f2tf32(Qs[m * QLD + k]);
            unsigned a1 = f2tf32(Qs[(m + 8) * QLD + k]);
            unsigned a2 = f2tf32(Qs[m * QLD + k + 4]);
            unsigned a3 = f2tf32(Qs[(m + 8) * QLD + k + 4]);
            #pragma unroll
            for (int nt = 0; nt < 8; nt++) {
                int n = nt * 8 + gid;
                unsigned b0 = f2tf32(Ks[n * KLD + k]);
                unsigned b1 = f2tf32(Ks[n * KLD + k + 4]);
                mma_tf32(sc[nt], a0, a1, a2, a3, b0, b1);
            }
        }

        // ---- online softmax ----
        const float scale = 0.125f;
        float ml0 = -1e30f, ml1 = -1e30f;
        #pragma unroll
        for (int nt = 0; nt < 8; nt++) {
            int coln = kBase + nt * 8 + 2 * tig;
            #pragma unroll
            for (int cc = 0; cc < 4; cc++) {
                float v = sc[nt][cc] * scale;
                if (causal) {
                    int col = coln + (cc & 1);
                    int row = (cc < 2) ? row0g : (row0g + 8);
                    if (col > row) v = -1e30f;
                }
                sc[nt][cc] = v;
                if (cc < 2) ml0 = fmaxf(ml0, v);
                else        ml1 = fmaxf(ml1, v);
            }
        }
        #pragma unroll
        for (int off = 1; off < 4; off <<= 1) {
            ml0 = fmaxf(ml0, __shfl_xor_sync(0xffffffffu, ml0, off));
            ml1 = fmaxf(ml1, __shfl_xor_sync(0xffffffffu, ml1, off));
        }
        float mn0 = fmaxf(mrow0, ml0), mn1 = fmaxf(mrow1, ml1);
        float al0 = __expf(mrow0 - mn0), al1 = __expf(mrow1 - mn1);
        mrow0 = mn0; mrow1 = mn1;

        float rs0 = 0.0f, rs1 = 0.0f;
        #pragma unroll
        for (int nt = 0; nt < 8; nt++) {
            float p0 = __expf(sc[nt][0] - mn0);
            float p1 = __expf(sc[nt][1] - mn0);
            float p2 = __expf(sc[nt][2] - mn1);
            float p3 = __expf(sc[nt][3] - mn1);
            sc[nt][0] = p0; sc[nt][1] = p1; sc[nt][2] = p2; sc[nt][3] = p3;
            rs0 += p0 + p1; rs1 += p2 + p3;
        }
        #pragma unroll
        for (int off = 1; off < 4; off <<= 1) {
            rs0 += __shfl_xor_sync(0xffffffffu, rs0, off);
            rs1 += __shfl_xor_sync(0xffffffffu, rs1, off);
        }
        lrow0 = lrow0 * al0 + rs0;
        lrow1 = lrow1 * al1 + rs1;
        #pragma unroll
        for (int dt = 0; dt < 8; dt++) {
            of[dt][0] *= al0; of[dt][1] *= al0;
            of[dt][2] *= al1; of[dt][3] *= al1;
        }

        // ---- Phase B: O += P V ----
        const int l0 = (lane & 28) | (tig >> 1);
        const int l1 = l0 + 2;
        const bool odd = (tig & 1);
        #pragma unroll
        for (int kt = 0; kt < 8; kt++) {
            float p00 = __shfl_sync(0xffffffffu, sc[kt][0], l0);
            float p01 = __shfl_sync(0xffffffffu, sc[kt][1], l0);
            float p10 = __shfl_sync(0xffffffffu, sc[kt][2], l0);
            float p11 = __shfl_sync(0xffffffffu, sc[kt][3], l0);
            float q00 = __shfl_sync(0xffffffffu, sc[kt][0], l1);
            float q01 = __shfl_sync(0xffffffffu, sc[kt][1], l1);
            float q10 = __shfl_sync(0xffffffffu, sc[kt][2], l1);
            float q11 = __shfl_sync(0xffffffffu, sc[kt][3], l1);
            unsigned a0 = f2tf32(odd ? p01 : p00);
            unsigned a1 = f2tf32(odd ? p11 : p10);
            unsigned a2 = f2tf32(odd ? q01 : q00);
            unsigned a3 = f2tf32(odd ? q11 : q10);
            #pragma unroll
            for (int dt = 0; dt < 8; dt++) {
                unsigned b0 = f2tf32(Vs[(kt * 8 + tig) * VLD + dt * 8 + gid]);
                unsigned b1 = f2tf32(Vs[(kt * 8 + tig + 4) * VLD + dt * 8 + gid]);
                mma_tf32(of[dt], a0, a1, a2, a3, b0, b1);
            }
        }
        __syncthreads();
    }

    // Epilogue
    float inv0 = 1.0f / lrow0, inv1 = 1.0f / lrow1;
    float* op = out + (size_t)b * S_LEN * DMODEL + h * HD;
    #pragma unroll
    for (int dt = 0; dt < 8; dt++) {
        int col = dt * 8 + 2 * tig;
        float2 w0 = {of[dt][0] * inv0, of[dt][1] * inv0};
        float2 w1 = {of[dt][2] * inv1, of[dt][3] * inv1};
        *(float2*)(op + (size_t)row0g * DMODEL + col)       = w0;
        *(float2*)(op + (size_t)(row0g + 8) * DMODEL + col) = w1;
    }
}

// ---------------------------------------------------------------------------
extern "C" void kernel_launch(void* const* d_in, const int* in_sizes, int n_in,
                              void* d_out, int out_size)
{
    (void)in_sizes; (void)n_in; (void)out_size;
    const float* features = (const float*)d_in[0];
    const float* qkv_w    = (const float*)d_in[1];
    const float* qkv_b    = (const float*)d_in[2];
    const float* out_w    = (const float*)d_in[3];
    const float* out_b    = (const float*)d_in[4];
    const int*   causal   = (const int*)d_in[5];
    float* out = (float*)d_out;

    float* qkvbuf = nullptr;
    float* attbuf = nullptr;
    cudaGetSymbolAddress((void**)&qkvbuf, g_qkv);
    cudaGetSymbolAddress((void**)&attbuf, g_att);

    const int SMEM_GEMM  = GSTAGES * GSTAGE * (int)sizeof(float);   // 110592
    const int SMEM_FLASH = (Q_FLOATS + 2 * K_FLOATS + 2 * V_FLOATS)
                           * (int)sizeof(float);                     // 106496

    cudaFuncSetAttribute(gemm_tc<3 * DMODEL, DMODEL>,
                         cudaFuncAttributeMaxDynamicSharedMemorySize, SMEM_GEMM);
    cudaFuncSetAttribute(gemm_tc<DMODEL, DMODEL>,
                         cudaFuncAttributeMaxDynamicSharedMemorySize, SMEM_GEMM);
    cudaFuncSetAttribute(flash_attn_tc,
                         cudaFuncAttributeMaxDynamicSharedMemorySize, SMEM_FLASH);

    // 1) QKV projection
    gemm_tc<3 * DMODEL, DMODEL>
        <<<dim3(3 * DMODEL / 128, BATCH * S_LEN / 128), 256, SMEM_GEMM>>>(
            features, qkv_w, qkv_b, qkvbuf);

    // 2) Attention
    flash_attn_tc<<<dim3(S_LEN / 128, NH, BATCH), 256, SMEM_FLASH>>>(
        qkvbuf, attbuf, causal);

    // 3) Output projection
    gemm_tc<DMODEL, DMODEL>
        <<<dim3(DMODEL / 128, BATCH * S_LEN / 128), 256, SMEM_GEMM>>>(
            attbuf, out_w, out_b, out);
}

// round 8
// speedup vs baseline: 3.6364x; 1.0096x over previous
#include <cuda_runtime.h>
#include <cstdint>
#include <stdint.h>
#include <math.h>

#define S_LEN  2048
#define BATCH  2
#define DMODEL 1024
#define NH     16
#define HD     64

// Scratch (allocation-free requirement)
__device__ float g_qkv[BATCH * S_LEN * 3 * DMODEL];        // [b, s, 3d] (tf32-rounded)
__device__ float g_att[BATCH * S_LEN * DMODEL];            // features-rounded, then attn out
__device__ float g_w[4 * DMODEL * DMODEL];                 // rounded qkv_w | out_w

// ---------------------------------------------------------------------------
// helpers
// ---------------------------------------------------------------------------
__device__ __forceinline__ unsigned f2tf32(float f) {
    unsigned u;
    asm("cvt.rna.tf32.f32 %0, %1;" : "=r"(u) : "f"(f));
    return u;
}
__device__ __forceinline__ float tf32f(float f) {
    return __uint_as_float(f2tf32(f));
}
__device__ __forceinline__ void mma_tf32(float c[4], unsigned a0, unsigned a1,
                                         unsigned a2, unsigned a3,
                                         unsigned b0, unsigned b1) {
    asm("mma.sync.aligned.m16n8k8.row.col.f32.tf32.tf32.f32 "
        "{%0,%1,%2,%3}, {%4,%5,%6,%7}, {%8,%9}, {%0,%1,%2,%3};"
        : "+f"(c[0]), "+f"(c[1]), "+f"(c[2]), "+f"(c[3])
        : "r"(a0), "r"(a1), "r"(a2), "r"(a3), "r"(b0), "r"(b1));
}
__device__ __forceinline__ void cp_async16(unsigned int dst, const void* src) {
    asm volatile("cp.async.cg.shared.global [%0], [%1], 16;" :: "r"(dst), "l"(src));
}
__device__ __forceinline__ void cp_commit() {
    asm volatile("cp.async.commit_group;");
}
template<int N>
__device__ __forceinline__ void cp_wait() {
    asm volatile("cp.async.wait_group %0;" :: "n"(N));
}

// ---------------------------------------------------------------------------
// Elementwise tf32 rounding (idempotent): out[i] = round_rna_tf32(in[i])
// ---------------------------------------------------------------------------
__global__ void round_tf32_kernel(const float4* __restrict__ in,
                                  float4* __restrict__ out, int n4)
{
    int i = blockIdx.x * blockDim.x + threadIdx.x;
    if (i < n4) {
        float4 v = in[i];
        v.x = tf32f(v.x); v.y = tf32f(v.y);
        v.z = tf32f(v.z); v.w = tf32f(v.w);
        out[i] = v;
    }
}

// ---------------------------------------------------------------------------
// TF32 tensor-core GEMM, 3-stage cp.async pipeline, ONE sync per k-tile.
// Inputs A, B are pre-rounded to tf32 values -> no cvt in the inner loop.
// C[M,N] = A[M,K]*B[N,K]^T + bias[N];  ROUND: round outputs to tf32 values.
// ---------------------------------------------------------------------------
#define GSTG (128 * 36)
#define GSTAGE (2 * GSTG)
#define GSTAGES 3

template<int N_, int K_, bool ROUND>
__global__ __launch_bounds__(256, 1)
void gemm_tc(const float* __restrict__ A, const float* __restrict__ B,
             const float* __restrict__ bias, float* __restrict__ C)
{
    extern __shared__ float sm[];
    const unsigned int smAddr = (unsigned int)__cvta_generic_to_shared(sm);

    const int tid  = threadIdx.x;
    const int warp = tid >> 5;
    const int lane = tid & 31;
    const int gid  = lane >> 2;
    const int tig  = lane & 3;
    const int warpM = (warp & 1) * 64;
    const int warpN = (warp >> 1) * 32;
    const int mBase = blockIdx.y * 128;
    const int nBase = blockIdx.x * 128;

    int lrow[4], lcol[4];
    #pragma unroll
    for (int i = 0; i < 4; i++) {
        int s4 = tid + i * 256;
        lrow[i] = s4 >> 3;
        lcol[i] = (s4 & 7) * 4;
    }

    auto issue_stage = [&](int stage, int k0) {
        unsigned int aB = smAddr + stage * GSTAGE * 4;
        unsigned int bB = aB + GSTG * 4;
        #pragma unroll
        for (int i = 0; i < 4; i++) {
            unsigned int off = (lrow[i] * 36 + lcol[i]) * 4;
            cp_async16(aB + off, A + (size_t)(mBase + lrow[i]) * K_ + k0 + lcol[i]);
            cp_async16(bB + off, B + (size_t)(nBase + lrow[i]) * K_ + k0 + lcol[i]);
        }
    };

    float acc[16][4];
    #pragma unroll
    for (int i = 0; i < 16; i++)
        #pragma unroll
        for (int j = 0; j < 4; j++) acc[i][j] = 0.0f;

    const int kTiles = K_ / 32;
    #pragma unroll
    for (int s = 0; s < GSTAGES - 1; s++) {
        issue_stage(s, s * 32);
        cp_commit();
    }

    for (int kt = 0; kt < kTiles; kt++) {
        if (kt == kTiles - 1) cp_wait<0>();
        else                  cp_wait<GSTAGES - 2>();   // tile kt resident (FIFO)
        __syncthreads();   // also proves all warps finished MMAs of kt-1,
                           // so the stage we are about to overwrite is free
        if (kt + GSTAGES - 1 < kTiles) {
            issue_stage((kt + GSTAGES - 1) % GSTAGES, (kt + GSTAGES - 1) * 32);
            cp_commit();
        }

        const float* As = sm + (kt % GSTAGES) * GSTAGE;
        const float* Bs = As + GSTG;

        #pragma unroll
        for (int ks = 0; ks < 4; ks++) {
            unsigned afr[4][4], bfr[4][2];
            #pragma unroll
            for (int mt = 0; mt < 4; mt++) {
                int m = warpM + mt * 16 + gid;
                int k = ks * 8 + tig;
                afr[mt][0] = __float_as_uint(As[m * 36 + k]);
                afr[mt][1] = __float_as_uint(As[(m + 8) * 36 + k]);
                afr[mt][2] = __float_as_uint(As[m * 36 + k + 4]);
                afr[mt][3] = __float_as_uint(As[(m + 8) * 36 + k + 4]);
            }
            #pragma unroll
            for (int nt = 0; nt < 4; nt++) {
                int n = warpN + nt * 8 + gid;
                int k = ks * 8 + tig;
                bfr[nt][0] = __float_as_uint(Bs[n * 36 + k]);
                bfr[nt][1] = __float_as_uint(Bs[n * 36 + k + 4]);
            }
            #pragma unroll
            for (int mt = 0; mt < 4; mt++)
                #pragma unroll
                for (int nt = 0; nt < 4; nt++)
                    mma_tf32(acc[mt * 4 + nt], afr[mt][0], afr[mt][1],
                             afr[mt][2], afr[mt][3], bfr[nt][0], bfr[nt][1]);
        }
    }

    #pragma unroll
    for (int mt = 0; mt < 4; mt++) {
        #pragma unroll
        for (int nt = 0; nt < 4; nt++) {
            int row  = mBase + warpM + mt * 16 + gid;
            int coln = nBase + warpN + nt * 8 + 2 * tig;
            float b0 = bias[coln], b1 = bias[coln + 1];
            float* acc4 = acc[mt * 4 + nt];
            float2 w0, w1;
            if (ROUND) {
                w0.x = tf32f(acc4[0] + b0); w0.y = tf32f(acc4[1] + b1);
                w1.x = tf32f(acc4[2] + b0); w1.y = tf32f(acc4[3] + b1);
            } else {
                w0.x = acc4[0] + b0; w0.y = acc4[1] + b1;
                w1.x = acc4[2] + b0; w1.y = acc4[3] + b1;
            }
            *(float2*)(C + (size_t)row * N_ + coln)       = w0;
            *(float2*)(C + (size_t)(row + 8) * N_ + coln) = w1;
        }
    }
}

// ---------------------------------------------------------------------------
// TF32 flash attention; Q/K/V are pre-rounded (gemm1 epilogue) -> no cvt on
// their fragments. Double-buffered cp.async K/V, one sync per tile.
// Output rounded to tf32 (feeds gemm2 which does no cvt).
// ---------------------------------------------------------------------------
#define QLD 68
#define KLD 68
#define VLD 72
#define Q_FLOATS (128 * QLD)
#define K_FLOATS (64 * KLD)
#define V_FLOATS (64 * VLD)

__global__ __launch_bounds__(256, 1)
void flash_attn_tc(const float* __restrict__ qkv, float* __restrict__ out,
                   const int* __restrict__ causal_flag)
{
    extern __shared__ float sm[];
    float* Qs = sm;
    float* Kbuf = Qs + Q_FLOATS;
    float* Vbuf = Kbuf + 2 * K_FLOATS;
    const unsigned int smAddr = (unsigned int)__cvta_generic_to_shared(sm);
    const unsigned int kAddr0 = smAddr + Q_FLOATS * 4;
    const unsigned int vAddr0 = kAddr0 + 2 * K_FLOATS * 4;

    const int tid  = threadIdx.x;
    const int warp = tid >> 5;
    const int lane = tid & 31;
    const int gid  = lane >> 2;
    const int tig  = lane & 3;
    const int qBase = blockIdx.x * 128;
    const int h = blockIdx.y;
    const int b = blockIdx.z;
    const bool causal = (*causal_flag != 0);

    const int rowStride = 3 * DMODEL;
    const float* qp = qkv + (size_t)b * S_LEN * rowStride + h * HD;
    const float* kp = qp + DMODEL;
    const float* vp = qp + 2 * DMODEL;

    // 64x64 tile = 1024 float4 slots -> 4 per thread
    int kn[4], kc[4];
    #pragma unroll
    for (int i = 0; i < 4; i++) {
        int s4 = tid + i * 256;
        kn[i] = s4 >> 4;
        kc[i] = (s4 & 15) * 4;
    }
    auto issue_kv = [&](int buf, int kBase) {
        unsigned int kB = kAddr0 + buf * K_FLOATS * 4;
        unsigned int vB = vAddr0 + buf * V_FLOATS * 4;
        #pragma unroll
        for (int i = 0; i < 4; i++) {
            size_t g = (size_t)(kBase + kn[i]) * rowStride + kc[i];
            cp_async16(kB + (kn[i] * KLD + kc[i]) * 4, kp + g);
            cp_async16(vB + (kn[i] * VLD + kc[i]) * 4, vp + g);
        }
    };

    int nTiles = S_LEN / 64;
    if (causal) nTiles = (qBase + 128) / 64;

    issue_kv(0, 0);
    cp_commit();

    #pragma unroll
    for (int i = 0; i < 8; i++) {
        int s4 = tid + i * 256;
        int m  = s4 >> 4;
        int c  = (s4 & 15) * 4;
        *(float4*)&Qs[m * QLD + c] =
            *(const float4*)(qp + (size_t)(qBase + m) * rowStride + c);
    }

    float of[8][4];
    #pragma unroll
    for (int i = 0; i < 8; i++)
        #pragma unroll
        for (int j = 0; j < 4; j++) of[i][j] = 0.0f;
    float mrow0 = -1e30f, mrow1 = -1e30f, lrow0 = 0.0f, lrow1 = 0.0f;

    const int row0g = qBase + warp * 16 + gid;

    for (int t = 0; t < nTiles; t++) {
        const int kBase = t * 64;
        const int buf   = t & 1;

        cp_wait<0>();          // exactly one group pending: tile t
        __syncthreads();       // all warps done with buffer buf^1 (tile t-1)
        if (t + 1 < nTiles) {
            issue_kv(1 - buf, kBase + 64);
            cp_commit();
        }

        const float* Ks = Kbuf + buf * K_FLOATS;
        const float* Vs = Vbuf + buf * V_FLOATS;

        // ---- Phase A: S = Q K^T (operands pre-rounded, no cvt) ----
        float sc[8][4];
        #pragma unroll
        for (int i = 0; i < 8; i++)
            #pragma unroll
            for (int j = 0; j < 4; j++) sc[i][j] = 0.0f;

        #pragma unroll
        for (int ks = 0; ks < 8; ks++) {
            int m = warp * 16 + gid;
            int k = ks * 8 + tig;
            unsigned a0 = __float_as_uint(Qs[m * QLD + k]);
            unsigned a1 = __float_as_uint(Qs[(m + 8) * QLD + k]);
            unsigned a2 = __float_as_uint(Qs[m * QLD + k + 4]);
            unsigned a3 = __float_as_uint(Qs[(m + 8) * QLD + k + 4]);
            #pragma unroll
            for (int nt = 0; nt < 8; nt++) {
                int n = nt * 8 + gid;
                unsigned b0 = __float_as_uint(Ks[n * KLD + k]);
                unsigned b1 = __float_as_uint(Ks[n * KLD + k + 4]);
                mma_tf32(sc[nt], a0, a1, a2, a3, b0, b1);
            }
        }

        // ---- online softmax ----
        const float scale = 0.125f;
        float ml0 = -1e30f, ml1 = -1e30f;
        #pragma unroll
        for (int nt = 0; nt < 8; nt++) {
            int coln = kBase + nt * 8 + 2 * tig;
            #pragma unroll
            for (int cc = 0; cc < 4; cc++) {
                float v = sc[nt][cc] * scale;
                if (causal) {
                    int col = coln + (cc & 1);
                    int row = (cc < 2) ? row0g : (row0g + 8);
                    if (col > row) v = -1e30f;
                }
                sc[nt][cc] = v;
                if (cc < 2) ml0 = fmaxf(ml0, v);
                else        ml1 = fmaxf(ml1, v);
            }
        }
        #pragma unroll
        for (int off = 1; off < 4; off <<= 1) {
            ml0 = fmaxf(ml0, __shfl_xor_sync(0xffffffffu, ml0, off));
            ml1 = fmaxf(ml1, __shfl_xor_sync(0xffffffffu, ml1, off));
        }
        float mn0 = fmaxf(mrow0, ml0), mn1 = fmaxf(mrow1, ml1);
        float al0 = __expf(mrow0 - mn0), al1 = __expf(mrow1 - mn1);
        mrow0 = mn0; mrow1 = mn1;

        float rs0 = 0.0f, rs1 = 0.0f;
        #pragma unroll
        for (int nt = 0; nt < 8; nt++) {
            float p0 = __expf(sc[nt][0] - mn0);
            float p1 = __expf(sc[nt][1] - mn0);
            float p2 = __expf(sc[nt][2] - mn1);
            float p3 = __expf(sc[nt][3] - mn1);
            sc[nt][0] = p0; sc[nt][1] = p1; sc[nt][2] = p2; sc[nt][3] = p3;
            rs0 += p0 + p1; rs1 += p2 + p3;
        }
        #pragma unroll
        for (int off = 1; off < 4; off <<= 1) {
            rs0 += __shfl_xor_sync(0xffffffffu, rs0, off);
            rs1 += __shfl_xor_sync(0xffffffffu, rs1, off);
        }
        lrow0 = lrow0 * al0 + rs0;
        lrow1 = lrow1 * al1 + rs1;
        #pragma unroll
        for (int dt = 0; dt < 8; dt++) {
            of[dt][0] *= al0; of[dt][1] *= al0;
            of[dt][2] *= al1; of[dt][3] *= al1;
        }

        // ---- Phase B: O += P V (only P needs cvt) ----
        const int l0 = (lane & 28) | (tig >> 1);
        const int l1 = l0 + 2;
        const bool odd = (tig & 1);
        #pragma unroll
        for (int kt = 0; kt < 8; kt++) {
            float p00 = __shfl_sync(0xffffffffu, sc[kt][0], l0);
            float p01 = __shfl_sync(0xffffffffu, sc[kt][1], l0);
            float p10 = __shfl_sync(0xffffffffu, sc[kt][2], l0);
            float p11 = __shfl_sync(0xffffffffu, sc[kt][3], l0);
            float q00 = __shfl_sync(0xffffffffu, sc[kt][0], l1);
            float q01 = __shfl_sync(0xffffffffu, sc[kt][1], l1);
            float q10 = __shfl_sync(0xffffffffu, sc[kt][2], l1);
            float q11 = __shfl_sync(0xffffffffu, sc[kt][3], l1);
            unsigned a0 = f2tf32(odd ? p01 : p00);
            unsigned a1 = f2tf32(odd ? p11 : p10);
            unsigned a2 = f2tf32(odd ? q01 : q00);
            unsigned a3 = f2tf32(odd ? q11 : q10);
            #pragma unroll
            for (int dt = 0; dt < 8; dt++) {
                unsigned b0 = __float_as_uint(Vs[(kt * 8 + tig) * VLD + dt * 8 + gid]);
                unsigned b1 = __float_as_uint(Vs[(kt * 8 + tig + 4) * VLD + dt * 8 + gid]);
                mma_tf32(of[dt], a0, a1, a2, a3, b0, b1);
            }
        }
    }

    // Epilogue: normalize, round to tf32 (gemm2 consumes without cvt)
    float inv0 = 1.0f / lrow0, inv1 = 1.0f / lrow1;
    float* op = out + (size_t)b * S_LEN * DMODEL + h * HD;
    #pragma unroll
    for (int dt = 0; dt < 8; dt++) {
        int col = dt * 8 + 2 * tig;
        float2 w0, w1;
        w0.x = tf32f(of[dt][0] * inv0); w0.y = tf32f(of[dt][1] * inv0);
        w1.x = tf32f(of[dt][2] * inv1); w1.y = tf32f(of[dt][3] * inv1);
        *(float2*)(op + (size_t)row0g * DMODEL + col)       = w0;
        *(float2*)(op + (size_t)(row0g + 8) * DMODEL + col) = w1;
    }
}

// ---------------------------------------------------------------------------
extern "C" void kernel_launch(void* const* d_in, const int* in_sizes, int n_in,
                              void* d_out, int out_size)
{
    (void)in_sizes; (void)n_in; (void)out_size;
    const float* features = (const float*)d_in[0];
    const float* qkv_w    = (const float*)d_in[1];
    const float* qkv_b    = (const float*)d_in[2];
    const float* out_w    = (const float*)d_in[3];
    const float* out_b    = (const float*)d_in[4];
    const int*   causal   = (const int*)d_in[5];
    float* out = (float*)d_out;

    float* qkvbuf = nullptr;
    float* attbuf = nullptr;
    float* wbuf   = nullptr;
    cudaGetSymbolAddress((void**)&qkvbuf, g_qkv);
    cudaGetSymbolAddress((void**)&attbuf, g_att);
    cudaGetSymbolAddress((void**)&wbuf,   g_w);

    const int SMEM_GEMM  = GSTAGES * GSTAGE * (int)sizeof(float);   // 110592
    const int SMEM_FLASH = (Q_FLOATS + 2 * K_FLOATS + 2 * V_FLOATS)
                           * (int)sizeof(float);                     // 106496

    cudaFuncSetAttribute(gemm_tc<3 * DMODEL, DMODEL, true>,
                         cudaFuncAttributeMaxDynamicSharedMemorySize, SMEM_GEMM);
    cudaFuncSetAttribute(gemm_tc<DMODEL, DMODEL, false>,
                         cudaFuncAttributeMaxDynamicSharedMemorySize, SMEM_GEMM);
    cudaFuncSetAttribute(flash_attn_tc,
                         cudaFuncAttributeMaxDynamicSharedMemorySize, SMEM_FLASH);

    // 0) pre-round inputs to tf32 values (idempotent, same numerics as per-use cvt)
    {
        int nF = BATCH * S_LEN * DMODEL / 4;          // features -> g_att
        round_tf32_kernel<<<(nF + 255) / 256, 256>>>(
            (const float4*)features, (float4*)attbuf, nF);
        int nW1 = 3 * DMODEL * DMODEL / 4;            // qkv_w -> g_w[0]
        round_tf32_kernel<<<(nW1 + 255) / 256, 256>>>(
            (const float4*)qkv_w, (float4*)wbuf, nW1);
        int nW2 = DMODEL * DMODEL / 4;                // out_w -> g_w[3*D*D]
        round_tf32_kernel<<<(nW2 + 255) / 256, 256>>>(
            (const float4*)out_w, (float4*)(wbuf + 3 * DMODEL * DMODEL), nW2);
    }

    // 1) QKV projection (rounded output feeds attention)
    gemm_tc<3 * DMODEL, DMODEL, true>
        <<<dim3(3 * DMODEL / 128, BATCH * S_LEN / 128), 256, SMEM_GEMM>>>(
            attbuf, wbuf, qkv_b, qkvbuf);

    // 2) Attention (reads rounded qkv, writes rounded output over g_att)
    flash_attn_tc<<<dim3(S_LEN / 128, NH, BATCH), 256, SMEM_FLASH>>>(
        qkvbuf, attbuf, causal);

    // 3) Output projection (exact fp32 output)
    gemm_tc<DMODEL, DMODEL, false>
        <<<dim3(DMODEL / 128, BATCH * S_LEN / 128), 256, SMEM_GEMM>>>(
            attbuf, wbuf + 3 * DMODEL * DMODEL, out_b, out);
}

// round 9
// speedup vs baseline: 4.0781x; 1.1215x over previous
#include <cuda_runtime.h>
#include <cstdint>
#include <stdint.h>
#include <math.h>

#define S_LEN  2048
#define BATCH  2
#define DMODEL 1024
#define NH     16
#define HD     64

// Scratch (allocation-free requirement)
__device__ float g_qkv[BATCH * S_LEN * 3 * DMODEL];        // [b, s, 3d] (tf32-rounded)
__device__ float g_att[BATCH * S_LEN * DMODEL];            // features-rounded, then attn out
__device__ float g_w[4 * DMODEL * DMODEL];                 // rounded qkv_w | out_w

// ---------------------------------------------------------------------------
// helpers
// ---------------------------------------------------------------------------
__device__ __forceinline__ unsigned f2tf32(float f) {
    unsigned u;
    asm("cvt.rna.tf32.f32 %0, %1;" : "=r"(u) : "f"(f));
    return u;
}
__device__ __forceinline__ float tf32f(float f) {
    return __uint_as_float(f2tf32(f));
}
__device__ __forceinline__ void mma_tf32(float c[4], unsigned a0, unsigned a1,
                                         unsigned a2, unsigned a3,
                                         unsigned b0, unsigned b1) {
    asm("mma.sync.aligned.m16n8k8.row.col.f32.tf32.tf32.f32 "
        "{%0,%1,%2,%3}, {%4,%5,%6,%7}, {%8,%9}, {%0,%1,%2,%3};"
        : "+f"(c[0]), "+f"(c[1]), "+f"(c[2]), "+f"(c[3])
        : "r"(a0), "r"(a1), "r"(a2), "r"(a3), "r"(b0), "r"(b1));
}
__device__ __forceinline__ void cp_async16(unsigned int dst, const void* src) {
    asm volatile("cp.async.cg.shared.global [%0], [%1], 16;" :: "r"(dst), "l"(src));
}
__device__ __forceinline__ void cp_commit() {
    asm volatile("cp.async.commit_group;");
}
template<int N>
__device__ __forceinline__ void cp_wait() {
    asm volatile("cp.async.wait_group %0;" :: "n"(N));
}

// ---------------------------------------------------------------------------
// Elementwise tf32 rounding (idempotent): out[i] = round_rna_tf32(in[i])
// ---------------------------------------------------------------------------
__global__ void round_tf32_kernel(const float4* __restrict__ in,
                                  float4* __restrict__ out, int n4)
{
    int i = blockIdx.x * blockDim.x + threadIdx.x;
    if (i < n4) {
        float4 v = in[i];
        v.x = tf32f(v.x); v.y = tf32f(v.y);
        v.z = tf32f(v.z); v.w = tf32f(v.w);
        out[i] = v;
    }
}

// ---------------------------------------------------------------------------
// TF32 tensor-core GEMM, 3-stage cp.async pipeline, ONE sync per k-tile.
// Inputs A, B are pre-rounded to tf32 values -> no cvt in the inner loop.
// __launch_bounds__(256,2): cap regs at 128 so 2 CTAs/SM (smem 2x108KB fits).
// ---------------------------------------------------------------------------
#define GSTG (128 * 36)
#define GSTAGE (2 * GSTG)
#define GSTAGES 3

template<int N_, int K_, bool ROUND>
__global__ __launch_bounds__(256, 2)
void gemm_tc(const float* __restrict__ A, const float* __restrict__ B,
             const float* __restrict__ bias, float* __restrict__ C)
{
    extern __shared__ float sm[];
    const unsigned int smAddr = (unsigned int)__cvta_generic_to_shared(sm);

    const int tid  = threadIdx.x;
    const int warp = tid >> 5;
    const int lane = tid & 31;
    const int gid  = lane >> 2;
    const int tig  = lane & 3;
    const int warpM = (warp & 1) * 64;
    const int warpN = (warp >> 1) * 32;
    const int mBase = blockIdx.y * 128;
    const int nBase = blockIdx.x * 128;

    int lrow[4], lcol[4];
    #pragma unroll
    for (int i = 0; i < 4; i++) {
        int s4 = tid + i * 256;
        lrow[i] = s4 >> 3;
        lcol[i] = (s4 & 7) * 4;
    }

    auto issue_stage = [&](int stage, int k0) {
        unsigned int aB = smAddr + stage * GSTAGE * 4;
        unsigned int bB = aB + GSTG * 4;
        #pragma unroll
        for (int i = 0; i < 4; i++) {
            unsigned int off = (lrow[i] * 36 + lcol[i]) * 4;
            cp_async16(aB + off, A + (size_t)(mBase + lrow[i]) * K_ + k0 + lcol[i]);
            cp_async16(bB + off, B + (size_t)(nBase + lrow[i]) * K_ + k0 + lcol[i]);
        }
    };

    float acc[16][4];
    #pragma unroll
    for (int i = 0; i < 16; i++)
        #pragma unroll
        for (int j = 0; j < 4; j++) acc[i][j] = 0.0f;

    const int kTiles = K_ / 32;
    #pragma unroll
    for (int s = 0; s < GSTAGES - 1; s++) {
        issue_stage(s, s * 32);
        cp_commit();
    }

    for (int kt = 0; kt < kTiles; kt++) {
        if (kt == kTiles - 1) cp_wait<0>();
        else                  cp_wait<GSTAGES - 2>();   // tile kt resident (FIFO)
        __syncthreads();   // also proves all warps finished MMAs of kt-1,
                           // so the stage we are about to overwrite is free
        if (kt + GSTAGES - 1 < kTiles) {
            issue_stage((kt + GSTAGES - 1) % GSTAGES, (kt + GSTAGES - 1) * 32);
            cp_commit();
        }

        const float* As = sm + (kt % GSTAGES) * GSTAGE;
        const float* Bs = As + GSTG;

        #pragma unroll
        for (int ks = 0; ks < 4; ks++) {
            unsigned afr[4][4], bfr[4][2];
            #pragma unroll
            for (int mt = 0; mt < 4; mt++) {
                int m = warpM + mt * 16 + gid;
                int k = ks * 8 + tig;
                afr[mt][0] = __float_as_uint(As[m * 36 + k]);
                afr[mt][1] = __float_as_uint(As[(m + 8) * 36 + k]);
                afr[mt][2] = __float_as_uint(As[m * 36 + k + 4]);
                afr[mt][3] = __float_as_uint(As[(m + 8) * 36 + k + 4]);
            }
            #pragma unroll
            for (int nt = 0; nt < 4; nt++) {
                int n = warpN + nt * 8 + gid;
                int k = ks * 8 + tig;
                bfr[nt][0] = __float_as_uint(Bs[n * 36 + k]);
                bfr[nt][1] = __float_as_uint(Bs[n * 36 + k + 4]);
            }
            #pragma unroll
            for (int mt = 0; mt < 4; mt++)
                #pragma unroll
                for (int nt = 0; nt < 4; nt++)
                    mma_tf32(acc[mt * 4 + nt], afr[mt][0], afr[mt][1],
                             afr[mt][2], afr[mt][3], bfr[nt][0], bfr[nt][1]);
        }
    }

    #pragma unroll
    for (int mt = 0; mt < 4; mt++) {
        #pragma unroll
        for (int nt = 0; nt < 4; nt++) {
            int row  = mBase + warpM + mt * 16 + gid;
            int coln = nBase + warpN + nt * 8 + 2 * tig;
            float b0 = bias[coln], b1 = bias[coln + 1];
            float* acc4 = acc[mt * 4 + nt];
            float2 w0, w1;
            if (ROUND) {
                w0.x = tf32f(acc4[0] + b0); w0.y = tf32f(acc4[1] + b1);
                w1.x = tf32f(acc4[2] + b0); w1.y = tf32f(acc4[3] + b1);
            } else {
                w0.x = acc4[0] + b0; w0.y = acc4[1] + b1;
                w1.x = acc4[2] + b0; w1.y = acc4[3] + b1;
            }
            *(float2*)(C + (size_t)row * N_ + coln)       = w0;
            *(float2*)(C + (size_t)(row + 8) * N_ + coln) = w1;
        }
    }
}

// ---------------------------------------------------------------------------
// TF32 flash attention; Q/K/V pre-rounded -> no cvt on their fragments.
// Double-buffered cp.async K/V, one sync per tile, 2 CTAs/SM.
// ---------------------------------------------------------------------------
#define QLD 68
#define KLD 68
#define VLD 72
#define Q_FLOATS (128 * QLD)
#define K_FLOATS (64 * KLD)
#define V_FLOATS (64 * VLD)

__global__ __launch_bounds__(256, 2)
void flash_attn_tc(const float* __restrict__ qkv, float* __restrict__ out,
                   const int* __restrict__ causal_flag)
{
    extern __shared__ float sm[];
    float* Qs = sm;
    float* Kbuf = Qs + Q_FLOATS;
    float* Vbuf = Kbuf + 2 * K_FLOATS;
    const unsigned int smAddr = (unsigned int)__cvta_generic_to_shared(sm);
    const unsigned int kAddr0 = smAddr + Q_FLOATS * 4;
    const unsigned int vAddr0 = kAddr0 + 2 * K_FLOATS * 4;

    const int tid  = threadIdx.x;
    const int warp = tid >> 5;
    const int lane = tid & 31;
    const int gid  = lane >> 2;
    const int tig  = lane & 3;
    const int qBase = blockIdx.x * 128;
    const int h = blockIdx.y;
    const int b = blockIdx.z;
    const bool causal = (*causal_flag != 0);

    const int rowStride = 3 * DMODEL;
    const float* qp = qkv + (size_t)b * S_LEN * rowStride + h * HD;
    const float* kp = qp + DMODEL;
    const float* vp = qp + 2 * DMODEL;

    // 64x64 tile = 1024 float4 slots -> 4 per thread
    int kn[4], kc[4];
    #pragma unroll
    for (int i = 0; i < 4; i++) {
        int s4 = tid + i * 256;
        kn[i] = s4 >> 4;
        kc[i] = (s4 & 15) * 4;
    }
    auto issue_kv = [&](int buf, int kBase) {
        unsigned int kB = kAddr0 + buf * K_FLOATS * 4;
        unsigned int vB = vAddr0 + buf * V_FLOATS * 4;
        #pragma unroll
        for (int i = 0; i < 4; i++) {
            size_t g = (size_t)(kBase + kn[i]) * rowStride + kc[i];
            cp_async16(kB + (kn[i] * KLD + kc[i]) * 4, kp + g);
            cp_async16(vB + (kn[i] * VLD + kc[i]) * 4, vp + g);
        }
    };

    int nTiles = S_LEN / 64;
    if (causal) nTiles = (qBase + 128) / 64;

    issue_kv(0, 0);
    cp_commit();

    #pragma unroll
    for (int i = 0; i < 8; i++) {
        int s4 = tid + i * 256;
        int m  = s4 >> 4;
        int c  = (s4 & 15) * 4;
        *(float4*)&Qs[m * QLD + c] =
            *(const float4*)(qp + (size_t)(qBase + m) * rowStride + c);
    }

    float of[8][4];
    #pragma unroll
    for (int i = 0; i < 8; i++)
        #pragma unroll
        for (int j = 0; j < 4; j++) of[i][j] = 0.0f;
    float mrow0 = -1e30f, mrow1 = -1e30f, lrow0 = 0.0f, lrow1 = 0.0f;

    const int row0g = qBase + warp * 16 + gid;

    for (int t = 0; t < nTiles; t++) {
        const int kBase = t * 64;
        const int buf   = t & 1;

        cp_wait<0>();          // exactly one group pending: tile t
        __syncthreads();       // all warps done with buffer buf^1 (tile t-1)
        if (t + 1 < nTiles) {
            issue_kv(1 - buf, kBase + 64);
            cp_commit();
        }

        const float* Ks = Kbuf + buf * K_FLOATS;
        const float* Vs = Vbuf + buf * V_FLOATS;

        // ---- Phase A: S = Q K^T (operands pre-rounded, no cvt) ----
        float sc[8][4];
        #pragma unroll
        for (int i = 0; i < 8; i++)
            #pragma unroll
            for (int j = 0; j < 4; j++) sc[i][j] = 0.0f;

        #pragma unroll
        for (int ks = 0; ks < 8; ks++) {
            int m = warp * 16 + gid;
            int k = ks * 8 + tig;
            unsigned a0 = __float_as_uint(Qs[m * QLD + k]);
            unsigned a1 = __float_as_uint(Qs[(m + 8) * QLD + k]);
            unsigned a2 = __float_as_uint(Qs[m * QLD + k + 4]);
            unsigned a3 = __float_as_uint(Qs[(m + 8) * QLD + k + 4]);
            #pragma unroll
            for (int nt = 0; nt < 8; nt++) {
                int n = nt * 8 + gid;
                unsigned b0 = __float_as_uint(Ks[n * KLD + k]);
                unsigned b1 = __float_as_uint(Ks[n * KLD + k + 4]);
                mma_tf32(sc[nt], a0, a1, a2, a3, b0, b1);
            }
        }

        // ---- online softmax ----
        const float scale = 0.125f;
        float ml0 = -1e30f, ml1 = -1e30f;
        #pragma unroll
        for (int nt = 0; nt < 8; nt++) {
            int coln = kBase + nt * 8 + 2 * tig;
            #pragma unroll
            for (int cc = 0; cc < 4; cc++) {
                float v = sc[nt][cc] * scale;
                if (causal) {
                    int col = coln + (cc & 1);
                    int row = (cc < 2) ? row0g : (row0g + 8);
                    if (col > row) v = -1e30f;
                }
                sc[nt][cc] = v;
                if (cc < 2) ml0 = fmaxf(ml0, v);
                else        ml1 = fmaxf(ml1, v);
            }
        }
        #pragma unroll
        for (int off = 1; off < 4; off <<= 1) {
            ml0 = fmaxf(ml0, __shfl_xor_sync(0xffffffffu, ml0, off));
            ml1 = fmaxf(ml1, __shfl_xor_sync(0xffffffffu, ml1, off));
        }
        float mn0 = fmaxf(mrow0, ml0), mn1 = fmaxf(mrow1, ml1);
        float al0 = __expf(mrow0 - mn0), al1 = __expf(mrow1 - mn1);
        mrow0 = mn0; mrow1 = mn1;

        float rs0 = 0.0f, rs1 = 0.0f;
        #pragma unroll
        for (int nt = 0; nt < 8; nt++) {
            float p0 = __expf(sc[nt][0] - mn0);
            float p1 = __expf(sc[nt][1] - mn0);
            float p2 = __expf(sc[nt][2] - mn1);
            float p3 = __expf(sc[nt][3] - mn1);
            sc[nt][0] = p0; sc[nt][1] = p1; sc[nt][2] = p2; sc[nt][3] = p3;
            rs0 += p0 + p1; rs1 += p2 + p3;
        }
        #pragma unroll
        for (int off = 1; off < 4; off <<= 1) {
            rs0 += __shfl_xor_sync(0xffffffffu, rs0, off);
            rs1 += __shfl_xor_sync(0xffffffffu, rs1, off);
        }
        lrow0 = lrow0 * al0 + rs0;
        lrow1 = lrow1 * al1 + rs1;
        #pragma unroll
        for (int dt = 0; dt < 8; dt++) {
            of[dt][0] *= al0; of[dt][1] *= al0;
            of[dt][2] *= al1; of[dt][3] *= al1;
        }

        // ---- Phase B: O += P V (only P needs cvt) ----
        const int l0 = (lane & 28) | (tig >> 1);
        const int l1 = l0 + 2;
        const bool odd = (tig & 1);
        #pragma unroll
        for (int kt = 0; kt < 8; kt++) {
            float p00 = __shfl_sync(0xffffffffu, sc[kt][0], l0);
            float p01 = __shfl_sync(0xffffffffu, sc[kt][1], l0);
            float p10 = __shfl_sync(0xffffffffu, sc[kt][2], l0);
            float p11 = __shfl_sync(0xffffffffu, sc[kt][3], l0);
            float q00 = __shfl_sync(0xffffffffu, sc[kt][0], l1);
            float q01 = __shfl_sync(0xffffffffu, sc[kt][1], l1);
            float q10 = __shfl_sync(0xffffffffu, sc[kt][2], l1);
            float q11 = __shfl_sync(0xffffffffu, sc[kt][3], l1);
            unsigned a0 = f2tf32(odd ? p01 : p00);
            unsigned a1 = f2tf32(odd ? p11 : p10);
            unsigned a2 = f2tf32(odd ? q01 : q00);
            unsigned a3 = f2tf32(odd ? q11 : q10);
            #pragma unroll
            for (int dt = 0; dt < 8; dt++) {
                unsigned b0 = __float_as_uint(Vs[(kt * 8 + tig) * VLD + dt * 8 + gid]);
                unsigned b1 = __float_as_uint(Vs[(kt * 8 + tig + 4) * VLD + dt * 8 + gid]);
                mma_tf32(of[dt], a0, a1, a2, a3, b0, b1);
            }
        }
    }

    // Epilogue: normalize, round to tf32 (gemm2 consumes without cvt)
    float inv0 = 1.0f / lrow0, inv1 = 1.0f / lrow1;
    float* op = out + (size_t)b * S_LEN * DMODEL + h * HD;
    #pragma unroll
    for (int dt = 0; dt < 8; dt++) {
        int col = dt * 8 + 2 * tig;
        float2 w0, w1;
        w0.x = tf32f(of[dt][0] * inv0); w0.y = tf32f(of[dt][1] * inv0);
        w1.x = tf32f(of[dt][2] * inv1); w1.y = tf32f(of[dt][3] * inv1);
        *(float2*)(op + (size_t)row0g * DMODEL + col)       = w0;
        *(float2*)(op + (size_t)(row0g + 8) * DMODEL + col) = w1;
    }
}

// ---------------------------------------------------------------------------
extern "C" void kernel_launch(void* const* d_in, const int* in_sizes, int n_in,
                              void* d_out, int out_size)
{
    (void)in_sizes; (void)n_in; (void)out_size;
    const float* features = (const float*)d_in[0];
    const float* qkv_w    = (const float*)d_in[1];
    const float* qkv_b    = (const float*)d_in[2];
    const float* out_w    = (const float*)d_in[3];
    const float* out_b    = (const float*)d_in[4];
    const int*   causal   = (const int*)d_in[5];
    float* out = (float*)d_out;

    float* qkvbuf = nullptr;
    float* attbuf = nullptr;
    float* wbuf   = nullptr;
    cudaGetSymbolAddress((void**)&qkvbuf, g_qkv);
    cudaGetSymbolAddress((void**)&attbuf, g_att);
    cudaGetSymbolAddress((void**)&wbuf,   g_w);

    const int SMEM_GEMM  = GSTAGES * GSTAGE * (int)sizeof(float);   // 110592
    const int SMEM_FLASH = (Q_FLOATS + 2 * K_FLOATS + 2 * V_FLOATS)
                           * (int)sizeof(float);                     // 106496

    cudaFuncSetAttribute(gemm_tc<3 * DMODEL, DMODEL, true>,
                         cudaFuncAttributeMaxDynamicSharedMemorySize, SMEM_GEMM);
    cudaFuncSetAttribute(gemm_tc<DMODEL, DMODEL, false>,
                         cudaFuncAttributeMaxDynamicSharedMemorySize, SMEM_GEMM);
    cudaFuncSetAttribute(flash_attn_tc,
                         cudaFuncAttributeMaxDynamicSharedMemorySize, SMEM_FLASH);

    // 0) pre-round inputs to tf32 values (idempotent, same numerics as per-use cvt)
    {
        int nF = BATCH * S_LEN * DMODEL / 4;          // features -> g_att
        round_tf32_kernel<<<(nF + 255) / 256, 256>>>(
            (const float4*)features, (float4*)attbuf, nF);
        int nW1 = 3 * DMODEL * DMODEL / 4;            // qkv_w -> g_w[0]
        round_tf32_kernel<<<(nW1 + 255) / 256, 256>>>(
            (const float4*)qkv_w, (float4*)wbuf, nW1);
        int nW2 = DMODEL * DMODEL / 4;                // out_w -> g_w[3*D*D]
        round_tf32_kernel<<<(nW2 + 255) / 256, 256>>>(
            (const float4*)out_w, (float4*)(wbuf + 3 * DMODEL * DMODEL), nW2);
    }

    // 1) QKV projection (rounded output feeds attention)
    gemm_tc<3 * DMODEL, DMODEL, true>
        <<<dim3(3 * DMODEL / 128, BATCH * S_LEN / 128), 256, SMEM_GEMM>>>(
            attbuf, wbuf, qkv_b, qkvbuf);

    // 2) Attention (reads rounded qkv, writes rounded output over g_att)
    flash_attn_tc<<<dim3(S_LEN / 128, NH, BATCH), 256, SMEM_FLASH>>>(
        qkvbuf, attbuf, causal);

    // 3) Output projection (exact fp32 output)
    gemm_tc<DMODEL, DMODEL, false>
        <<<dim3(DMODEL / 128, BATCH * S_LEN / 128), 256, SMEM_GEMM>>>(
            attbuf, wbuf + 3 * DMODEL * DMODEL, out_b, out);
}

// round 11
// speedup vs baseline: 4.3975x; 1.0783x over previous
#include <cuda_runtime.h>
#include <cstdint>
#include <stdint.h>
#include <math.h>

#define S_LEN  2048
#define BATCH  2
#define DMODEL 1024
#define NH     16
#define HD     64

// Scratch (allocation-free requirement)
__device__ float g_qkv[BATCH * S_LEN * 3 * DMODEL];        // [b, s, 3d] (tf32-rounded)
__device__ float g_att[BATCH * S_LEN * DMODEL];            // features-rounded, then attn out
__device__ float g_w[4 * DMODEL * DMODEL];                 // rounded qkv_w | out_w

// ---------------------------------------------------------------------------
// helpers
// ---------------------------------------------------------------------------
__device__ __forceinline__ unsigned f2tf32(float f) {
    unsigned u;
    asm("cvt.rna.tf32.f32 %0, %1;" : "=r"(u) : "f"(f));
    return u;
}
__device__ __forceinline__ float tf32f(float f) {
    return __uint_as_float(f2tf32(f));
}
__device__ __forceinline__ void mma_tf32(float c[4], unsigned a0, unsigned a1,
                                         unsigned a2, unsigned a3,
                                         unsigned b0, unsigned b1) {
    asm("mma.sync.aligned.m16n8k8.row.col.f32.tf32.tf32.f32 "
        "{%0,%1,%2,%3}, {%4,%5,%6,%7}, {%8,%9}, {%0,%1,%2,%3};"
        : "+f"(c[0]), "+f"(c[1]), "+f"(c[2]), "+f"(c[3])
        : "r"(a0), "r"(a1), "r"(a2), "r"(a3), "r"(b0), "r"(b1));
}
__device__ __forceinline__ void ldsm_x4(unsigned& r0, unsigned& r1,
                                        unsigned& r2, unsigned& r3, unsigned addr) {
    asm volatile("ldmatrix.sync.aligned.m8n8.x4.shared.b16 {%0,%1,%2,%3}, [%4];"
                 : "=r"(r0), "=r"(r1), "=r"(r2), "=r"(r3) : "r"(addr));
}
__device__ __forceinline__ void ldsm_x2(unsigned& r0, unsigned& r1, unsigned addr) {
    asm volatile("ldmatrix.sync.aligned.m8n8.x2.shared.b16 {%0,%1}, [%2];"
                 : "=r"(r0), "=r"(r1) : "r"(addr));
}
__device__ __forceinline__ void cp_async16(unsigned int dst, const void* src) {
    asm volatile("cp.async.cg.shared.global [%0], [%1], 16;" :: "r"(dst), "l"(src));
}
__device__ __forceinline__ void cp_commit() {
    asm volatile("cp.async.commit_group;");
}
template<int N>
__device__ __forceinline__ void cp_wait() {
    asm volatile("cp.async.wait_group %0;" :: "n"(N));
}

// ---------------------------------------------------------------------------
// Fused elementwise tf32 rounding for features | qkv_w | out_w (idempotent)
// ---------------------------------------------------------------------------
#define NF4  (BATCH * S_LEN * DMODEL / 4)
#define NW14 (3 * DMODEL * DMODEL / 4)
#define NW24 (DMODEL * DMODEL / 4)

__global__ void round_all_kernel(const float4* __restrict__ f,
                                 const float4* __restrict__ w1,
                                 const float4* __restrict__ w2,
                                 float4* __restrict__ of,
                                 float4* __restrict__ ow1,
                                 float4* __restrict__ ow2)
{
    int i = blockIdx.x * blockDim.x + threadIdx.x;
    const float4* src; float4* dst; int j;
    if (i < NF4)                { src = f;  dst = of;  j = i; }
    else if (i < NF4 + NW14)    { src = w1; dst = ow1; j = i - NF4; }
    else if (i < NF4 + NW14 + NW24) { src = w2; dst = ow2; j = i - NF4 - NW14; }
    else return;
    float4 v = src[j];
    v.x = tf32f(v.x); v.y = tf32f(v.y);
    v.z = tf32f(v.z); v.w = tf32f(v.w);
    dst[j] = v;
}

// ---------------------------------------------------------------------------
// TF32 tensor-core GEMM, 3-stage cp.async pipeline, ldmatrix fragment loads.
// C[M,N] = A[M,K]*B[N,K]^T + bias[N].  Inputs pre-rounded to tf32.
// ---------------------------------------------------------------------------
#define GSTG (128 * 36)
#define GSTAGE (2 * GSTG)
#define GSTAGES 3

template<int N_, int K_, bool ROUND>
__global__ __launch_bounds__(256, 2)
void gemm_tc(const float* __restrict__ A, const float* __restrict__ B,
             const float* __restrict__ bias, float* __restrict__ C)
{
    extern __shared__ float sm[];
    const unsigned int smAddr = (unsigned int)__cvta_generic_to_shared(sm);

    const int tid  = threadIdx.x;
    const int warp = tid >> 5;
    const int lane = tid & 31;
    const int gid  = lane >> 2;
    const int tig  = lane & 3;
    const int warpM = (warp & 1) * 64;
    const int warpN = (warp >> 1) * 32;
    const int mBase = blockIdx.y * 128;
    const int nBase = blockIdx.x * 128;

    // ldmatrix per-lane row addresses (byte offsets within a stage)
    const int lg = lane >> 3;            // matrix group 0..3
    const int lr = lane & 7;             // row within matrix
    const unsigned aLdsmBase =
        (unsigned)(((warpM + (lg & 1) * 8 + lr) * 36 + (lg >> 1) * 4) * 4);
    const unsigned bLdsmBase =
        (unsigned)(((warpN + lr) * 36 + (lg & 1) * 4) * 4);

    int lrow[4], lcol[4];
    #pragma unroll
    for (int i = 0; i < 4; i++) {
        int s4 = tid + i * 256;
        lrow[i] = s4 >> 3;
        lcol[i] = (s4 & 7) * 4;
    }

    auto issue_stage = [&](int stage, int k0) {
        unsigned int aB = smAddr + stage * GSTAGE * 4;
        unsigned int bB = aB + GSTG * 4;
        #pragma unroll
        for (int i = 0; i < 4; i++) {
            unsigned int off = (lrow[i] * 36 + lcol[i]) * 4;
            cp_async16(aB + off, A + (size_t)(mBase + lrow[i]) * K_ + k0 + lcol[i]);
            cp_async16(bB + off, B + (size_t)(nBase + lrow[i]) * K_ + k0 + lcol[i]);
        }
    };

    float acc[16][4];
    #pragma unroll
    for (int i = 0; i < 16; i++)
        #pragma unroll
        for (int j = 0; j < 4; j++) acc[i][j] = 0.0f;

    const int kTiles = K_ / 32;
    #pragma unroll
    for (int s = 0; s < GSTAGES - 1; s++) {
        issue_stage(s, s * 32);
        cp_commit();
    }

    for (int kt = 0; kt < kTiles; kt++) {
        if (kt == kTiles - 1) cp_wait<0>();
        else                  cp_wait<GSTAGES - 2>();
        __syncthreads();
        if (kt + GSTAGES - 1 < kTiles) {
            issue_stage((kt + GSTAGES - 1) % GSTAGES, (kt + GSTAGES - 1) * 32);
            cp_commit();
        }

        const unsigned stA = smAddr + (kt % GSTAGES) * (GSTAGE * 4);
        const unsigned stB = stA + GSTG * 4;

        #pragma unroll
        for (int ks = 0; ks < 4; ks++) {
            unsigned afr[4][4], bfr[4][2];
            #pragma unroll
            for (int mt = 0; mt < 4; mt++)
                ldsm_x4(afr[mt][0], afr[mt][1], afr[mt][2], afr[mt][3],
                        stA + aLdsmBase + (unsigned)((mt * 16 * 36 + ks * 8) * 4));
            #pragma unroll
            for (int nt = 0; nt < 4; nt++)
                ldsm_x2(bfr[nt][0], bfr[nt][1],
                        stB + bLdsmBase + (unsigned)((nt * 8 * 36 + ks * 8) * 4));
            #pragma unroll
            for (int mt = 0; mt < 4; mt++)
                #pragma unroll
                for (int nt = 0; nt < 4; nt++)
                    mma_tf32(acc[mt * 4 + nt], afr[mt][0], afr[mt][1],
                             afr[mt][2], afr[mt][3], bfr[nt][0], bfr[nt][1]);
        }
    }

    #pragma unroll
    for (int mt = 0; mt < 4; mt++) {
        #pragma unroll
        for (int nt = 0; nt < 4; nt++) {
            int row  = mBase + warpM + mt * 16 + gid;
            int coln = nBase + warpN + nt * 8 + 2 * tig;
            float b0 = bias[coln], b1 = bias[coln + 1];
            float* acc4 = acc[mt * 4 + nt];
            float2 w0, w1;
            if (ROUND) {
                w0.x = tf32f(acc4[0] + b0); w0.y = tf32f(acc4[1] + b1);
                w1.x = tf32f(acc4[2] + b0); w1.y = tf32f(acc4[3] + b1);
            } else {
                w0.x = acc4[0] + b0; w0.y = acc4[1] + b1;
                w1.x = acc4[2] + b0; w1.y = acc4[3] + b1;
            }
            *(float2*)(C + (size_t)row * N_ + coln)       = w0;
            *(float2*)(C + (size_t)(row + 8) * N_ + coln) = w1;
        }
    }
}

// ---------------------------------------------------------------------------
// TF32 flash attention; ldmatrix for Q/K fragments, LDS.32 for V (k-major
// fragment can't use non-trans b32 ldmatrix). 1/8 scale folded into Q store
// (exact pow2 on tf32 values). Double-buffered cp.async K/V, 2 CTAs/SM.
// ---------------------------------------------------------------------------
#define QLD 68
#define KLD 68
#define VLD 72
#define Q_FLOATS (128 * QLD)
#define K_FLOATS (64 * KLD)
#define V_FLOATS (64 * VLD)

__global__ __launch_bounds__(256, 2)
void flash_attn_tc(const float* __restrict__ qkv, float* __restrict__ out,
                   const int* __restrict__ causal_flag)
{
    extern __shared__ float sm[];
    float* Qs = sm;
    float* Kbuf = Qs + Q_FLOATS;
    float* Vbuf = Kbuf + 2 * K_FLOATS;
    const unsigned int smAddr = (unsigned int)__cvta_generic_to_shared(sm);
    const unsigned int kAddr0 = smAddr + Q_FLOATS * 4;
    const unsigned int vAddr0 = kAddr0 + 2 * K_FLOATS * 4;

    const int tid  = threadIdx.x;
    const int warp = tid >> 5;
    const int lane = tid & 31;
    const int gid  = lane >> 2;
    const int tig  = lane & 3;
    const int qBase = blockIdx.x * 128;
    const int h = blockIdx.y;
    const int b = blockIdx.z;
    const bool causal = (*causal_flag != 0);

    const int rowStride = 3 * DMODEL;
    const float* qp = qkv + (size_t)b * S_LEN * rowStride + h * HD;
    const float* kp = qp + DMODEL;
    const float* vp = qp + 2 * DMODEL;

    // ldmatrix per-lane bases
    const int lg = lane >> 3;
    const int lr = lane & 7;
    const unsigned qLdsmBase = smAddr +
        (unsigned)(((warp * 16 + (lg & 1) * 8 + lr) * QLD + (lg >> 1) * 4) * 4);
    const unsigned kLdsmBase =
        (unsigned)((lr * KLD + (lg & 1) * 4) * 4);

    int kn[4], kc[4];
    #pragma unroll
    for (int i = 0; i < 4; i++) {
        int s4 = tid + i * 256;
        kn[i] = s4 >> 4;
        kc[i] = (s4 & 15) * 4;
    }
    auto issue_kv = [&](int buf, int kBase) {
        unsigned int kB = kAddr0 + buf * K_FLOATS * 4;
        unsigned int vB = vAddr0 + buf * V_FLOATS * 4;
        #pragma unroll
        for (int i = 0; i < 4; i++) {
            size_t g = (size_t)(kBase + kn[i]) * rowStride + kc[i];
            cp_async16(kB + (kn[i] * KLD + kc[i]) * 4, kp + g);
            cp_async16(vB + (kn[i] * VLD + kc[i]) * 4, vp + g);
        }
    };

    int nTiles = S_LEN / 64;
    if (causal) nTiles = (qBase + 128) / 64;

    issue_kv(0, 0);
    cp_commit();

    // Q load with folded 1/8 scale (exact on tf32 values)
    #pragma unroll
    for (int i = 0; i < 8; i++) {
        int s4 = tid + i * 256;
        int m  = s4 >> 4;
        int c  = (s4 & 15) * 4;
        float4 v = *(const float4*)(qp + (size_t)(qBase + m) * rowStride + c);
        v.x *= 0.125f; v.y *= 0.125f; v.z *= 0.125f; v.w *= 0.125f;
        *(float4*)&Qs[m * QLD + c] = v;
    }

    float of[8][4];
    #pragma unroll
    for (int i = 0; i < 8; i++)
        #pragma unroll
        for (int j = 0; j < 4; j++) of[i][j] = 0.0f;
    float mrow0 = -1e30f, mrow1 = -1e30f, lrow0 = 0.0f, lrow1 = 0.0f;

    const int row0g = qBase + warp * 16 + gid;

    for (int t = 0; t < nTiles; t++) {
        const int kBase = t * 64;
        const int buf   = t & 1;

        cp_wait<0>();
        __syncthreads();
        if (t + 1 < nTiles) {
            issue_kv(1 - buf, kBase + 64);
            cp_commit();
        }

        const unsigned kStage = kAddr0 + buf * K_FLOATS * 4;
        const float* Vs = Vbuf + buf * V_FLOATS;

        // ---- Phase A: S = (Q/8) K^T via ldmatrix fragments ----
        float sc[8][4];
        #pragma unroll
        for (int i = 0; i < 8; i++)
            #pragma unroll
            for (int j = 0; j < 4; j++) sc[i][j] = 0.0f;

        #pragma unroll
        for (int ks = 0; ks < 8; ks++) {
            unsigned a0, a1, a2, a3;
            ldsm_x4(a0, a1, a2, a3, qLdsmBase + (unsigned)(ks * 32));
            #pragma unroll
            for (int nt = 0; nt < 8; nt++) {
                unsigned b0, b1;
                ldsm_x2(b0, b1,
                        kStage + kLdsmBase + (unsigned)((nt * 8 * KLD + ks * 8) * 4));
                mma_tf32(sc[nt], a0, a1, a2, a3, b0, b1);
            }
        }

        // ---- online softmax (values already scaled) ----
        float ml0 = -1e30f, ml1 = -1e30f;
        #pragma unroll
        for (int nt = 0; nt < 8; nt++) {
            int coln = kBase + nt * 8 + 2 * tig;
            #pragma unroll
            for (int cc = 0; cc < 4; cc++) {
                float v = sc[nt][cc];
                if (causal) {
                    int col = coln + (cc & 1);
                    int row = (cc < 2) ? row0g : (row0g + 8);
                    if (col > row) v = -1e30f;
                }
                sc[nt][cc] = v;
                if (cc < 2) ml0 = fmaxf(ml0, v);
                else        ml1 = fmaxf(ml1, v);
            }
        }
        #pragma unroll
        for (int off = 1; off < 4; off <<= 1) {
            ml0 = fmaxf(ml0, __shfl_xor_sync(0xffffffffu, ml0, off));
            ml1 = fmaxf(ml1, __shfl_xor_sync(0xffffffffu, ml1, off));
        }
        float mn0 = fmaxf(mrow0, ml0), mn1 = fmaxf(mrow1, ml1);
        float al0 = __expf(mrow0 - mn0), al1 = __expf(mrow1 - mn1);
        mrow0 = mn0; mrow1 = mn1;

        float rs0 = 0.0f, rs1 = 0.0f;
        #pragma unroll
        for (int nt = 0; nt < 8; nt++) {
            float p0 = __expf(sc[nt][0] - mn0);
            float p1 = __expf(sc[nt][1] - mn0);
            float p2 = __expf(sc[nt][2] - mn1);
            float p3 = __expf(sc[nt][3] - mn1);
            sc[nt][0] = p0; sc[nt][1] = p1; sc[nt][2] = p2; sc[nt][3] = p3;
            rs0 += p0 + p1; rs1 += p2 + p3;
        }
        #pragma unroll
        for (int off = 1; off < 4; off <<= 1) {
            rs0 += __shfl_xor_sync(0xffffffffu, rs0, off);
            rs1 += __shfl_xor_sync(0xffffffffu, rs1, off);
        }
        lrow0 = lrow0 * al0 + rs0;
        lrow1 = lrow1 * al1 + rs1;
        #pragma unroll
        for (int dt = 0; dt < 8; dt++) {
            of[dt][0] *= al0; of[dt][1] *= al0;
            of[dt][2] *= al1; of[dt][3] *= al1;
        }

        // ---- Phase B: O += P V (P via shuffles, V via LDS.32) ----
        const int l0 = (lane & 28) | (tig >> 1);
        const int l1 = l0 + 2;
        const bool odd = (tig & 1);
        #pragma unroll
        for (int kt = 0; kt < 8; kt++) {
            float p00 = __shfl_sync(0xffffffffu, sc[kt][0], l0);
            float p01 = __shfl_sync(0xffffffffu, sc[kt][1], l0);
            float p10 = __shfl_sync(0xffffffffu, sc[kt][2], l0);
            float p11 = __shfl_sync(0xffffffffu, sc[kt][3], l0);
            float q00 = __shfl_sync(0xffffffffu, sc[kt][0], l1);
            float q01 = __shfl_sync(0xffffffffu, sc[kt][1], l1);
            float q10 = __shfl_sync(0xffffffffu, sc[kt][2], l1);
            float q11 = __shfl_sync(0xffffffffu, sc[kt][3], l1);
            unsigned a0 = f2tf32(odd ? p01 : p00);
            unsigned a1 = f2tf32(odd ? p11 : p10);
            unsigned a2 = f2tf32(odd ? q01 : q00);
            unsigned a3 = f2tf32(odd ? q11 : q10);
            #pragma unroll
            for (int dt = 0; dt < 8; dt++) {
                unsigned b0 = __float_as_uint(Vs[(kt * 8 + tig) * VLD + dt * 8 + gid]);
                unsigned b1 = __float_as_uint(Vs[(kt * 8 + tig + 4) * VLD + dt * 8 + gid]);
                mma_tf32(of[dt], a0, a1, a2, a3, b0, b1);
            }
        }
    }

    // Epilogue: normalize, round to tf32 (gemm2 consumes without cvt)
    float inv0 = 1.0f / lrow0, inv1 = 1.0f / lrow1;
    float* op = out + (size_t)b * S_LEN * DMODEL + h * HD;
    #pragma unroll
    for (int dt = 0; dt < 8; dt++) {
        int col = dt * 8 + 2 * tig;
        float2 w0, w1;
        w0.x = tf32f(of[dt][0] * inv0); w0.y = tf32f(of[dt][1] * inv0);
        w1.x = tf32f(of[dt][2] * inv1); w1.y = tf32f(of[dt][3] * inv1);
        *(float2*)(op + (size_t)row0g * DMODEL + col)       = w0;
        *(float2*)(op + (size_t)(row0g + 8) * DMODEL + col) = w1;
    }
}

// ---------------------------------------------------------------------------
extern "C" void kernel_launch(void* const* d_in, const int* in_sizes, int n_in,
                              void* d_out, int out_size)
{
    (void)in_sizes; (void)n_in; (void)out_size;
    const float* features = (const float*)d_in[0];
    const float* qkv_w    = (const float*)d_in[1];
    const float* qkv_b    = (const float*)d_in[2];
    const float* out_w    = (const float*)d_in[3];
    const float* out_b    = (const float*)d_in[4];
    const int*   causal   = (const int*)d_in[5];
    float* out = (float*)d_out;

    float* qkvbuf = nullptr;
    float* attbuf = nullptr;
    float* wbuf   = nullptr;
    cudaGetSymbolAddress((void**)&qkvbuf, g_qkv);
    cudaGetSymbolAddress((void**)&attbuf, g_att);
    cudaGetSymbolAddress((void**)&wbuf,   g_w);

    const int SMEM_GEMM  = GSTAGES * GSTAGE * (int)sizeof(float);   // 110592
    const int SMEM_FLASH = (Q_FLOATS + 2 * K_FLOATS + 2 * V_FLOATS)
                           * (int)sizeof(float);                     // 106496

    cudaFuncSetAttribute(gemm_tc<3 * DMODEL, DMODEL, true>,
                         cudaFuncAttributeMaxDynamicSharedMemorySize, SMEM_GEMM);
    cudaFuncSetAttribute(gemm_tc<DMODEL, DMODEL, false>,
                         cudaFuncAttributeMaxDynamicSharedMemorySize, SMEM_GEMM);
    cudaFuncSetAttribute(flash_attn_tc,
                         cudaFuncAttributeMaxDynamicSharedMemorySize, SMEM_FLASH);

    // 0) fused pre-rounding of all inputs to tf32 values
    {
        int total4 = NF4 + NW14 + NW24;
        round_all_kernel<<<(total4 + 255) / 256, 256>>>(
            (const float4*)features, (const float4*)qkv_w, (const float4*)out_w,
            (float4*)attbuf, (float4*)wbuf,
            (float4*)(wbuf + 3 * DMODEL * DMODEL));
    }

    // 1) QKV projection (rounded output feeds attention)
    gemm_tc<3 * DMODEL, DMODEL, true>
        <<<dim3(3 * DMODEL / 128, BATCH * S_LEN / 128), 256, SMEM_GEMM>>>(
            attbuf, wbuf, qkv_b, qkvbuf);

    // 2) Attention (reads rounded qkv, writes rounded output over g_att)
    flash_attn_tc<<<dim3(S_LEN / 128, NH, BATCH), 256, SMEM_FLASH>>>(
        qkvbuf, attbuf, causal);

    // 3) Output projection (exact fp32 output)
    gemm_tc<DMODEL, DMODEL, false>
        <<<dim3(DMODEL / 128, BATCH * S_LEN / 128), 256, SMEM_GEMM>>>(
            attbuf, wbuf + 3 * DMODEL * DMODEL, out_b, out);
}